// round 10
// baseline (speedup 1.0000x reference)
#include <cuda_runtime.h>
#include <cuda_fp16.h>
#include <cstdint>

// ---------------------------------------------------------------------------
// HVGGBlock in tangent space; convs via mma.sync m16n8k16 fp16 implicit GEMM.
// Channel-last fp16 intermediates; logmap fused into conv1 build; BN+clamp+
// relu fused into conv2 build. Fully-unrolled K loop + B-fragment pipelining.
//   logmap0(project(expmap0(u))) == clampnorm(u, R), R = artanh(1-1e-4)
// ---------------------------------------------------------------------------

#define NB   8
#define CH   32
#define HH   256
#define WW   256
#define PLANE (HH*WW)
#define IMG   (CH*PLANE)
#define NPIX  (NB*PLANE)

#define R_CLAMP 4.9517188f
#define MAXN    0.9999f

__device__ __align__(16) __half g_bufB[NB*IMG];   // channel-last: [pix][32]
__device__ __align__(16) __half g_bufA[NB*IMG];   // channel-last
__device__ float g_stats[128];   // [0:32) sum1 [32:64) sq1 [64:96) sum2 [96:128) sq2
__device__ __align__(16) uint32_t g_wpack[2*18*4*32*2];  // fp16 B-frags

__global__ void noop_kernel() {}   // profiler launch-alignment

// ---- weight pack: [layer][step][Nt][lane] -> {b0,b1} fp16x2 ------------------
__global__ void __launch_bounds__(256) pack_w_kernel(const float* __restrict__ w1,
                                                     const float* __restrict__ w2) {
    int id = blockIdx.x * 256 + threadIdx.x;
    if (id >= 4608) return;
    int lay = id / 2304;
    int r   = id - lay * 2304;
    int l   = r & 31;
    int Nt  = (r >> 5) & 3;
    int st  = r >> 7;                 // 0..17
    int t   = st >> 1, s2 = st & 1;
    int tig = l & 3, gid = l >> 2;
    int co  = Nt * 8 + gid;
    int ch0 = s2 * 16 + 2 * tig;
    const float* w = lay ? w2 : w1;
    __half2 h0 = __floats2half2_rn(w[(co * CH + ch0    ) * 9 + t],
                                   w[(co * CH + ch0 + 1) * 9 + t]);
    __half2 h1 = __floats2half2_rn(w[(co * CH + ch0 + 8) * 9 + t],
                                   w[(co * CH + ch0 + 9) * 9 + t]);
    uint2* dst = (uint2*)(g_wpack + lay * 4608);
    dst[(st * 4 + Nt) * 32 + l] = make_uint2(*(const uint32_t*)&h0,
                                             *(const uint32_t*)&h1);
}

__global__ void zero_stats_kernel() {
    int t = threadIdx.x;
    if (t < 128) g_stats[t] = 0.f;
}

// ---- fused conv kernel -------------------------------------------------------
#define PSTRIDE 621
#define SMEM_BYTES (8*PSTRIDE*8)     // 39744 dynamic

// MODE 0: src = x (fp32 NCHW), logmap, dst = g_bufB (fp16 ch-last)
// MODE 1: src = g_bufB, BN(stats[0:64])+clamp+relu, dst = g_bufA
template<int MODE>
__global__ void __launch_bounds__(256, 2)
conv_fused_kernel(const float* __restrict__ ext, const float* __restrict__ bias,
                  const float* __restrict__ gamma, const float* __restrict__ beta) {
    extern __shared__ __align__(16) uint2 s_in[];   // [8][PSTRIDE]
    __shared__ float s_aff[64];

    const int tid  = threadIdx.x;
    const int wid  = tid >> 5;
    const int lane = tid & 31;
    const int gid  = lane >> 2;
    const int tig  = lane & 3;
    const int n    = blockIdx.z;
    const int gy0  = blockIdx.y * 16;
    const int gx0  = blockIdx.x * 32;

    if (MODE == 1) {
        if (tid < 32) {
            const float inv = 1.0f / (float)NPIX;
            float m   = g_stats[tid] * inv;
            float var = fmaxf(g_stats[32 + tid] * inv - m * m, 0.f);
            float is  = rsqrtf(var + 1e-5f);
            float sc  = gamma[tid] * is;
            s_aff[tid]      = sc;
            s_aff[32 + tid] = beta[tid] - m * sc;
        }
        __syncthreads();
    }

    // ---- build: quad-cooperative (4 lanes per pixel, 8 channels per lane) ----
    const int lq = tid & 3;          // channels 8*lq .. 8*lq+7
    const int c0 = lq * 8;

    // hoist BN-affine into registers (loop-invariant; avoid per-pixel LDS)
    float affs[8], affb[8];
    if (MODE == 1) {
#pragma unroll
        for (int j = 0; j < 8; j++) {
            affs[j] = s_aff[c0 + j];
            affb[j] = s_aff[32 + c0 + j];
        }
    }

    uint32_t* sw = (uint32_t*)s_in;
    const int basew = ((lq >> 1) * 4) * PSTRIDE * 2 + (lq & 1);
    for (int p0 = tid >> 2; p0 < 640; p0 += 64) {
        bool act = (p0 < 612);
        int r = p0 / 34, c = p0 - r * 34;
        int gy = gy0 + r - 1, gx = gx0 + c - 1;
        bool inb = act && ((unsigned)gy < 256u) && ((unsigned)gx < 256u);
        float v[8]; float ss = 0.f;
        if (inb) {
            if (MODE == 0) {
                const float* sp = ext + n * IMG + c0 * PLANE + gy * WW + gx;
#pragma unroll
                for (int j = 0; j < 8; j++) { v[j] = sp[j * PLANE]; ss += v[j] * v[j]; }
            } else {
                uint4 hv = ((const uint4*)g_bufB)[(n * PLANE + gy * WW + gx) * 4 + lq];
                const uint32_t hw_[4] = {hv.x, hv.y, hv.z, hv.w};
#pragma unroll
                for (int j2 = 0; j2 < 4; j2++) {
                    float2 f = __half22float2(*(const __half2*)&hw_[j2]);
                    float u0 = f.x * affs[2*j2]     + affb[2*j2];
                    float u1 = f.y * affs[2*j2 + 1] + affb[2*j2 + 1];
                    v[2*j2] = u0; v[2*j2+1] = u1;
                    ss += u0 * u0 + u1 * u1;
                }
            }
        } else {
#pragma unroll
            for (int j = 0; j < 8; j++) v[j] = 0.f;
        }
        ss += __shfl_xor_sync(0xffffffffu, ss, 1);
        ss += __shfl_xor_sync(0xffffffffu, ss, 2);
        float f;
        if (MODE == 0) {
            float nrm = sqrtf(ss);
            float nn  = fmaxf(nrm, 1e-5f);
            float t   = fminf(nn, 1.f - 1e-5f);
            f = 0.5f * (log1pf(t) - log1pf(-t)) / nn;              // logmap0
        } else {
            float nrm = sqrtf(ss);
            f = (nrm > R_CLAMP) ? (R_CLAMP / nrm) : 1.0f;          // clampnorm
        }
        if (act) {
#pragma unroll
            for (int j = 0; j < 4; j++) {
                float u0 = v[2*j] * f, u1 = v[2*j+1] * f;
                if (MODE == 1) { u0 = fmaxf(u0, 0.f); u1 = fmaxf(u1, 0.f); }
                __half2 h = __floats2half2_rn(u0, u1);
                sw[basew + j * (PSTRIDE * 2) + p0 * 2] = *(const uint32_t*)&h;
            }
        }
    }
    __syncthreads();

    // ---- implicit GEMM: warp owns 2 pixel rows, 4 M-tiles, N=32, K=288 -------
    const uint2* wp = (const uint2*)(g_wpack + MODE * 4608) + lane;
    float acc[4][4][4];
#pragma unroll
    for (int i = 0; i < 4; i++)
#pragma unroll
        for (int Nt = 0; Nt < 4; Nt++)
#pragma unroll
            for (int j = 0; j < 4; j++) acc[i][Nt][j] = 0.f;

    const int warp_row = wid * 2;
    const int lanebase = warp_row * 34 + gid;   // lane's pixel anchor (ky=kx=0)

    // B-fragment pipeline: prefetch step 0
    uint2 bcur[4];
#pragma unroll
    for (int Nt = 0; Nt < 4; Nt++) bcur[Nt] = wp[(0 * 4 + Nt) * 32];

#pragma unroll
    for (int st = 0; st < 18; st++) {
        const int t  = st >> 1;
        const int s2 = st & 1;
        const int ky = (t >= 6) ? 2 : (t >= 3 ? 1 : 0);
        const int kx = t - ky * 3;

        uint2 bnxt[4];
        if (st < 17) {
#pragma unroll
            for (int Nt = 0; Nt < 4; Nt++) bnxt[Nt] = wp[((st + 1) * 4 + Nt) * 32];
        }

        const int pixbase = (s2 * 4 + tig) * PSTRIDE + lanebase + ky * 34 + kx;
#pragma unroll
        for (int i = 0; i < 4; i++) {
            int px = pixbase + (i >> 1) * 34 + (i & 1) * 16;
            uint2 A0 = s_in[px];
            uint2 A1 = s_in[px + 8];
#pragma unroll
            for (int Nt = 0; Nt < 4; Nt++) {
                asm volatile(
                    "mma.sync.aligned.m16n8k16.row.col.f32.f16.f16.f32 "
                    "{%0,%1,%2,%3}, {%4,%5,%6,%7}, {%8,%9}, {%0,%1,%2,%3};"
                    : "+f"(acc[i][Nt][0]), "+f"(acc[i][Nt][1]),
                      "+f"(acc[i][Nt][2]), "+f"(acc[i][Nt][3])
                    : "r"(A0.x), "r"(A1.x), "r"(A0.y), "r"(A1.y),
                      "r"(bcur[Nt].x), "r"(bcur[Nt].y));
            }
        }
        if (st < 17) {
#pragma unroll
            for (int Nt = 0; Nt < 4; Nt++) bcur[Nt] = bnxt[Nt];
        }
    }

    // ---- epilogue: bias + per-pixel clampnorm + half2 channel-last store -----
    float2 bs[4];
#pragma unroll
    for (int Nt = 0; Nt < 4; Nt++)
        bs[Nt] = *(const float2*)(bias + Nt * 8 + 2 * tig);

    uint32_t* o2 = (uint32_t*)(MODE == 0 ? g_bufB : g_bufA) + (size_t)n * PLANE * 16;
#pragma unroll
    for (int i = 0; i < 4; i++) {
        int yl = warp_row + (i >> 1);
        int xlA = (i & 1) * 16 + gid;
        float vA[8], vB[8];
        float ssA = 0.f, ssB = 0.f;
#pragma unroll
        for (int Nt = 0; Nt < 4; Nt++) {
            float a0 = acc[i][Nt][0] + bs[Nt].x;
            float a1 = acc[i][Nt][1] + bs[Nt].y;
            float b0 = acc[i][Nt][2] + bs[Nt].x;
            float b1 = acc[i][Nt][3] + bs[Nt].y;
            vA[2 * Nt] = a0; vA[2 * Nt + 1] = a1;
            vB[2 * Nt] = b0; vB[2 * Nt + 1] = b1;
            ssA += a0 * a0 + a1 * a1;
            ssB += b0 * b0 + b1 * b1;
        }
        ssA += __shfl_xor_sync(0xffffffffu, ssA, 1);
        ssA += __shfl_xor_sync(0xffffffffu, ssA, 2);
        ssB += __shfl_xor_sync(0xffffffffu, ssB, 1);
        ssB += __shfl_xor_sync(0xffffffffu, ssB, 2);
        float nA = sqrtf(ssA), nB = sqrtf(ssB);
        float fA = (nA > R_CLAMP) ? (R_CLAMP / nA) : 1.0f;
        float fB = (nB > R_CLAMP) ? (R_CLAMP / nB) : 1.0f;
        int pixA = (gy0 + yl) * WW + gx0 + xlA;
        int pixB = pixA + 8;
#pragma unroll
        for (int Nt = 0; Nt < 4; Nt++) {
            int cp = Nt * 4 + tig;
            __half2 hA = __floats2half2_rn(vA[2 * Nt] * fA, vA[2 * Nt + 1] * fA);
            __half2 hB = __floats2half2_rn(vB[2 * Nt] * fB, vB[2 * Nt + 1] * fB);
            o2[pixA * 16 + cp] = *(const uint32_t*)&hA;
            o2[pixB * 16 + cp] = *(const uint32_t*)&hB;
        }
    }
}

// ---- per-channel sum/sumsq over channel-last fp16 buffer ---------------------
__global__ void __launch_bounds__(256) stats_kernel(int statOff, int which) {
    const uint32_t* b2 = (const uint32_t*)(which ? g_bufA : g_bufB);
    const int cpair = threadIdx.x & 15;
    const int row   = threadIdx.x >> 4;
    const int base  = blockIdx.x * 1024;
    float s0 = 0.f, s1 = 0.f, q0 = 0.f, q1 = 0.f;
    for (int pp = row; pp < 1024; pp += 16) {
        uint32_t h = b2[(size_t)(base + pp) * 16 + cpair];
        float2 f = __half22float2(*(const __half2*)&h);
        s0 += f.x; q0 += f.x * f.x;
        s1 += f.y; q1 += f.y * f.y;
    }
    s0 += __shfl_xor_sync(0xffffffffu, s0, 16);
    s1 += __shfl_xor_sync(0xffffffffu, s1, 16);
    q0 += __shfl_xor_sync(0xffffffffu, q0, 16);
    q1 += __shfl_xor_sync(0xffffffffu, q1, 16);
    __shared__ float s_sum[64];
    if (threadIdx.x < 64) s_sum[threadIdx.x] = 0.f;
    __syncthreads();
    if ((threadIdx.x & 31) < 16) {
        atomicAdd(&s_sum[2 * cpair],      s0);
        atomicAdd(&s_sum[2 * cpair + 1],  s1);
        atomicAdd(&s_sum[32 + 2 * cpair],     q0);
        atomicAdd(&s_sum[32 + 2 * cpair + 1], q1);
    }
    __syncthreads();
    if (threadIdx.x < 64) atomicAdd(&g_stats[statOff + threadIdx.x], s_sum[threadIdx.x]);
}

// ---- bn2 + clamp + relu + expmap0 + project : bufA (ch-last) -> out (NCHW) ---
__global__ void __launch_bounds__(256) final_kernel(const float* __restrict__ gamma,
                                                    const float* __restrict__ beta,
                                                    float* __restrict__ out) {
    __shared__ float s_aff[64];
    if (threadIdx.x < 32) {
        int c = threadIdx.x;
        const float inv = 1.0f / (float)NPIX;
        float m   = g_stats[64 + c] * inv;
        float var = fmaxf(g_stats[96 + c] * inv - m * m, 0.f);
        float is  = rsqrtf(var + 1e-5f);
        float sc  = gamma[c] * is;
        s_aff[c]      = sc;
        s_aff[32 + c] = beta[c] - m * sc;
    }
    __syncthreads();

    int q  = blockIdx.x * 64 + (threadIdx.x >> 2);
    int lq = threadIdx.x & 3;
    int c0 = lq * 8;
    int n  = q >> 16, hw = q & 65535;

    uint4 hv = ((const uint4*)g_bufA)[(size_t)q * 4 + lq];
    const uint32_t hw_[4] = {hv.x, hv.y, hv.z, hv.w};
    float u[8]; float ss = 0.f;
#pragma unroll
    for (int j2 = 0; j2 < 4; j2++) {
        float2 f = __half22float2(*(const __half2*)&hw_[j2]);
        float u0 = f.x * s_aff[c0 + 2*j2]     + s_aff[32 + c0 + 2*j2];
        float u1 = f.y * s_aff[c0 + 2*j2 + 1] + s_aff[32 + c0 + 2*j2 + 1];
        u[2*j2] = u0; u[2*j2+1] = u1;
        ss += u0 * u0 + u1 * u1;
    }
    ss += __shfl_xor_sync(0xffffffffu, ss, 1);
    ss += __shfl_xor_sync(0xffffffffu, ss, 2);
    float nrm = sqrtf(ss);
    float f1 = (nrm > R_CLAMP) ? (R_CLAMP / nrm) : 1.0f;
    float ss2 = 0.f;
#pragma unroll
    for (int j = 0; j < 8; j++) { u[j] = fmaxf(u[j] * f1, 0.f); ss2 += u[j] * u[j]; }
    ss2 += __shfl_xor_sync(0xffffffffu, ss2, 1);
    ss2 += __shfl_xor_sync(0xffffffffu, ss2, 2);
    float nrm2 = sqrtf(ss2);
    float nn  = fmaxf(nrm2, 1e-5f);
    float fac = tanhf(nn) / nn;
    float yn  = fac * nrm2;
    float pm  = fmaxf(yn, 1e-5f);
    float g2  = (pm > MAXN) ? (MAXN / pm) : 1.0f;
    float wsc = fac * g2;
    float* op = out + (size_t)n * IMG + hw;
#pragma unroll
    for (int j = 0; j < 8; j++) op[(c0 + j) << 16] = u[j] * wsc;
}

// ---------------------------------------------------------------------------
extern "C" void kernel_launch(void* const* d_in, const int* in_sizes, int n_in,
                              void* d_out, int out_size) {
    const float* x   = (const float*)d_in[0];
    const float* w1  = (const float*)d_in[1];
    const float* b1  = (const float*)d_in[2];
    const float* g1  = (const float*)d_in[3];
    const float* be1 = (const float*)d_in[4];
    const float* w2  = (const float*)d_in[5];
    const float* b2  = (const float*)d_in[6];
    const float* g2  = (const float*)d_in[7];
    const float* be2 = (const float*)d_in[8];
    float* out = (float*)d_out;

    cudaFuncSetAttribute(conv_fused_kernel<0>,
                         cudaFuncAttributeMaxDynamicSharedMemorySize, SMEM_BYTES);
    cudaFuncSetAttribute(conv_fused_kernel<1>,
                         cudaFuncAttributeMaxDynamicSharedMemorySize, SMEM_BYTES);

    dim3 cgrid(WW / 32, HH / 16, NB);   // 8 x 16 x 8 = 1024 CTAs

    zero_stats_kernel<<<1, 128>>>();                               // 1
    noop_kernel<<<1, 32>>>();                                      // 2 (ncu align)
    pack_w_kernel<<<18, 256>>>(w1, w2);                            // 3

    conv_fused_kernel<0><<<cgrid, 256, SMEM_BYTES>>>(x, b1, nullptr, nullptr); // 4
    stats_kernel<<<512, 256>>>(0, 0);                              // 5

    conv_fused_kernel<1><<<cgrid, 256, SMEM_BYTES>>>(nullptr, b2, g1, be1);    // 6 <- profiled
    stats_kernel<<<512, 256>>>(64, 1);                             // 7

    final_kernel<<<NPIX / 64, 256>>>(g2, be2, out);                // 8
}

// round 11
// speedup vs baseline: 1.0442x; 1.0442x over previous
#include <cuda_runtime.h>
#include <cuda_fp16.h>
#include <cstdint>

// ---------------------------------------------------------------------------
// HVGGBlock in tangent space; convs via mma.sync m16n8k16 fp16 implicit GEMM.
// Channel-last fp16 intermediates; logmap fused into conv1 build; BN+clamp+
// relu fused into conv2 build. PSTRIDE=628 => plane stride ≡ 8 mod 32 banks:
// conflict-free A-fragment LDS.64 (621 gave 2-way conflicts).
//   logmap0(project(expmap0(u))) == clampnorm(u, R), R = artanh(1-1e-4)
// ---------------------------------------------------------------------------

#define NB   8
#define CH   32
#define HH   256
#define WW   256
#define PLANE (HH*WW)
#define IMG   (CH*PLANE)
#define NPIX  (NB*PLANE)

#define R_CLAMP 4.9517188f
#define MAXN    0.9999f

__device__ __align__(16) __half g_bufB[NB*IMG];   // channel-last: [pix][32]
__device__ __align__(16) __half g_bufA[NB*IMG];   // channel-last
__device__ float g_stats[128];   // [0:32) sum1 [32:64) sq1 [64:96) sum2 [96:128) sq2
__device__ __align__(16) uint32_t g_wpack[2*18*4*32*2];  // fp16 B-frags

__global__ void noop_kernel() {}   // profiler launch-alignment

// ---- weight pack: [layer][step][Nt][lane] -> {b0,b1} fp16x2 ------------------
__global__ void __launch_bounds__(256) pack_w_kernel(const float* __restrict__ w1,
                                                     const float* __restrict__ w2) {
    int id = blockIdx.x * 256 + threadIdx.x;
    if (id >= 4608) return;
    int lay = id / 2304;
    int r   = id - lay * 2304;
    int l   = r & 31;
    int Nt  = (r >> 5) & 3;
    int st  = r >> 7;                 // 0..17
    int t   = st >> 1, s2 = st & 1;
    int tig = l & 3, gid = l >> 2;
    int co  = Nt * 8 + gid;
    int ch0 = s2 * 16 + 2 * tig;
    const float* w = lay ? w2 : w1;
    __half2 h0 = __floats2half2_rn(w[(co * CH + ch0    ) * 9 + t],
                                   w[(co * CH + ch0 + 1) * 9 + t]);
    __half2 h1 = __floats2half2_rn(w[(co * CH + ch0 + 8) * 9 + t],
                                   w[(co * CH + ch0 + 9) * 9 + t]);
    uint2* dst = (uint2*)(g_wpack + lay * 4608);
    dst[(st * 4 + Nt) * 32 + l] = make_uint2(*(const uint32_t*)&h0,
                                             *(const uint32_t*)&h1);
}

__global__ void zero_stats_kernel() {
    int t = threadIdx.x;
    if (t < 128) g_stats[t] = 0.f;
}

// ---- fused conv kernel -------------------------------------------------------
// PSTRIDE*2 words = 1256 ≡ 8 (mod 32) -> tig-planes occupy disjoint bank octets
#define PSTRIDE 628
#define SMEM_BYTES (8*PSTRIDE*8)     // 40192 dynamic

// MODE 0: src = x (fp32 NCHW), logmap, dst = g_bufB (fp16 ch-last)
// MODE 1: src = g_bufB, BN(stats[0:64])+clamp+relu, dst = g_bufA
template<int MODE>
__global__ void __launch_bounds__(256, 2)
conv_fused_kernel(const float* __restrict__ ext, const float* __restrict__ bias,
                  const float* __restrict__ gamma, const float* __restrict__ beta) {
    extern __shared__ __align__(16) uint2 s_in[];   // [8][PSTRIDE]
    __shared__ float s_aff[64];

    const int tid  = threadIdx.x;
    const int wid  = tid >> 5;
    const int lane = tid & 31;
    const int gid  = lane >> 2;
    const int tig  = lane & 3;
    const int n    = blockIdx.z;
    const int gy0  = blockIdx.y * 16;
    const int gx0  = blockIdx.x * 32;

    if (MODE == 1) {
        if (tid < 32) {
            const float inv = 1.0f / (float)NPIX;
            float m   = g_stats[tid] * inv;
            float var = fmaxf(g_stats[32 + tid] * inv - m * m, 0.f);
            float is  = rsqrtf(var + 1e-5f);
            float sc  = gamma[tid] * is;
            s_aff[tid]      = sc;
            s_aff[32 + tid] = beta[tid] - m * sc;
        }
        __syncthreads();
    }

    // ---- build: quad-cooperative (4 lanes per pixel, 8 channels per lane) ----
    const int lq = tid & 3;          // channels 8*lq .. 8*lq+7
    const int c0 = lq * 8;
    uint32_t* sw = (uint32_t*)s_in;
    const int basew = ((lq >> 1) * 4) * PSTRIDE * 2 + (lq & 1);
    for (int p0 = tid >> 2; p0 < 640; p0 += 64) {
        bool act = (p0 < 612);
        int r = p0 / 34, c = p0 - r * 34;
        int gy = gy0 + r - 1, gx = gx0 + c - 1;
        bool inb = act && ((unsigned)gy < 256u) && ((unsigned)gx < 256u);
        float v[8]; float ss = 0.f;
        if (inb) {
            if (MODE == 0) {
                const float* sp = ext + n * IMG + c0 * PLANE + gy * WW + gx;
#pragma unroll
                for (int j = 0; j < 8; j++) { v[j] = sp[j * PLANE]; ss += v[j] * v[j]; }
            } else {
                uint4 hv = ((const uint4*)g_bufB)[(n * PLANE + gy * WW + gx) * 4 + lq];
                const uint32_t hw_[4] = {hv.x, hv.y, hv.z, hv.w};
#pragma unroll
                for (int j2 = 0; j2 < 4; j2++) {
                    float2 f = __half22float2(*(const __half2*)&hw_[j2]);
                    float u0 = f.x * s_aff[c0 + 2*j2]     + s_aff[32 + c0 + 2*j2];
                    float u1 = f.y * s_aff[c0 + 2*j2 + 1] + s_aff[32 + c0 + 2*j2 + 1];
                    v[2*j2] = u0; v[2*j2+1] = u1;
                    ss += u0 * u0 + u1 * u1;
                }
            }
        } else {
#pragma unroll
            for (int j = 0; j < 8; j++) v[j] = 0.f;
        }
        ss += __shfl_xor_sync(0xffffffffu, ss, 1);
        ss += __shfl_xor_sync(0xffffffffu, ss, 2);
        float f;
        if (MODE == 0) {
            float nrm = sqrtf(ss);
            float nn  = fmaxf(nrm, 1e-5f);
            float t   = fminf(nn, 1.f - 1e-5f);
            f = 0.5f * (log1pf(t) - log1pf(-t)) / nn;              // logmap0
        } else {
            float nrm = sqrtf(ss);
            f = (nrm > R_CLAMP) ? (R_CLAMP / nrm) : 1.0f;          // clampnorm
        }
        if (act) {
#pragma unroll
            for (int j = 0; j < 4; j++) {
                float u0 = v[2*j] * f, u1 = v[2*j+1] * f;
                if (MODE == 1) { u0 = fmaxf(u0, 0.f); u1 = fmaxf(u1, 0.f); }
                __half2 h = __floats2half2_rn(u0, u1);
                sw[basew + j * (PSTRIDE * 2) + p0 * 2] = *(const uint32_t*)&h;
            }
        }
    }
    __syncthreads();

    // ---- implicit GEMM: warp owns 2 pixel rows, 4 M-tiles, N=32, K=288 -------
    const uint2* wp = (const uint2*)(g_wpack + MODE * 4608);
    float acc[4][4][4];
#pragma unroll
    for (int i = 0; i < 4; i++)
#pragma unroll
        for (int Nt = 0; Nt < 4; Nt++)
#pragma unroll
            for (int j = 0; j < 4; j++) acc[i][Nt][j] = 0.f;

    const int warp_row = wid * 2;

#pragma unroll 6
    for (int st = 0; st < 18; st++) {
        int t  = st >> 1;
        int s2 = st & 1;
        int ky = (t >= 6) ? 2 : (t >= 3 ? 1 : 0);
        int kx = t - ky * 3;

        uint2 b[4];
#pragma unroll
        for (int Nt = 0; Nt < 4; Nt++) b[Nt] = wp[(st * 4 + Nt) * 32 + lane];

        int pixbase = (s2 * 4 + tig) * PSTRIDE + (warp_row + ky) * 34 + kx + gid;
#pragma unroll
        for (int i = 0; i < 4; i++) {
            int px = pixbase + (i >> 1) * 34 + (i & 1) * 16;
            uint2 A0 = s_in[px];
            uint2 A1 = s_in[px + 8];
#pragma unroll
            for (int Nt = 0; Nt < 4; Nt++) {
                asm volatile(
                    "mma.sync.aligned.m16n8k16.row.col.f32.f16.f16.f32 "
                    "{%0,%1,%2,%3}, {%4,%5,%6,%7}, {%8,%9}, {%0,%1,%2,%3};"
                    : "+f"(acc[i][Nt][0]), "+f"(acc[i][Nt][1]),
                      "+f"(acc[i][Nt][2]), "+f"(acc[i][Nt][3])
                    : "r"(A0.x), "r"(A1.x), "r"(A0.y), "r"(A1.y),
                      "r"(b[Nt].x), "r"(b[Nt].y));
            }
        }
    }

    // ---- epilogue: bias + per-pixel clampnorm + half2 channel-last store -----
    float2 bs[4];
#pragma unroll
    for (int Nt = 0; Nt < 4; Nt++)
        bs[Nt] = *(const float2*)(bias + Nt * 8 + 2 * tig);

    uint32_t* o2 = (uint32_t*)(MODE == 0 ? g_bufB : g_bufA) + (size_t)n * PLANE * 16;
#pragma unroll
    for (int i = 0; i < 4; i++) {
        int yl = warp_row + (i >> 1);
        int xlA = (i & 1) * 16 + gid;
        float vA[8], vB[8];
        float ssA = 0.f, ssB = 0.f;
#pragma unroll
        for (int Nt = 0; Nt < 4; Nt++) {
            float a0 = acc[i][Nt][0] + bs[Nt].x;
            float a1 = acc[i][Nt][1] + bs[Nt].y;
            float b0 = acc[i][Nt][2] + bs[Nt].x;
            float b1 = acc[i][Nt][3] + bs[Nt].y;
            vA[2 * Nt] = a0; vA[2 * Nt + 1] = a1;
            vB[2 * Nt] = b0; vB[2 * Nt + 1] = b1;
            ssA += a0 * a0 + a1 * a1;
            ssB += b0 * b0 + b1 * b1;
        }
        ssA += __shfl_xor_sync(0xffffffffu, ssA, 1);
        ssA += __shfl_xor_sync(0xffffffffu, ssA, 2);
        ssB += __shfl_xor_sync(0xffffffffu, ssB, 1);
        ssB += __shfl_xor_sync(0xffffffffu, ssB, 2);
        float nA = sqrtf(ssA), nB = sqrtf(ssB);
        float fA = (nA > R_CLAMP) ? (R_CLAMP / nA) : 1.0f;
        float fB = (nB > R_CLAMP) ? (R_CLAMP / nB) : 1.0f;
        int pixA = (gy0 + yl) * WW + gx0 + xlA;
        int pixB = pixA + 8;
#pragma unroll
        for (int Nt = 0; Nt < 4; Nt++) {
            int cp = Nt * 4 + tig;
            __half2 hA = __floats2half2_rn(vA[2 * Nt] * fA, vA[2 * Nt + 1] * fA);
            __half2 hB = __floats2half2_rn(vB[2 * Nt] * fB, vB[2 * Nt + 1] * fB);
            o2[pixA * 16 + cp] = *(const uint32_t*)&hA;
            o2[pixB * 16 + cp] = *(const uint32_t*)&hB;
        }
    }
}

// ---- per-channel sum/sumsq over channel-last fp16 buffer ---------------------
__global__ void __launch_bounds__(256) stats_kernel(int statOff, int which) {
    const uint32_t* b2 = (const uint32_t*)(which ? g_bufA : g_bufB);
    const int cpair = threadIdx.x & 15;
    const int row   = threadIdx.x >> 4;
    const int base  = blockIdx.x * 1024;
    float s0 = 0.f, s1 = 0.f, q0 = 0.f, q1 = 0.f;
    for (int pp = row; pp < 1024; pp += 16) {
        uint32_t h = b2[(size_t)(base + pp) * 16 + cpair];
        float2 f = __half22float2(*(const __half2*)&h);
        s0 += f.x; q0 += f.x * f.x;
        s1 += f.y; q1 += f.y * f.y;
    }
    s0 += __shfl_xor_sync(0xffffffffu, s0, 16);
    s1 += __shfl_xor_sync(0xffffffffu, s1, 16);
    q0 += __shfl_xor_sync(0xffffffffu, q0, 16);
    q1 += __shfl_xor_sync(0xffffffffu, q1, 16);
    __shared__ float s_sum[64];
    if (threadIdx.x < 64) s_sum[threadIdx.x] = 0.f;
    __syncthreads();
    if ((threadIdx.x & 31) < 16) {
        atomicAdd(&s_sum[2 * cpair],      s0);
        atomicAdd(&s_sum[2 * cpair + 1],  s1);
        atomicAdd(&s_sum[32 + 2 * cpair],     q0);
        atomicAdd(&s_sum[32 + 2 * cpair + 1], q1);
    }
    __syncthreads();
    if (threadIdx.x < 64) atomicAdd(&g_stats[statOff + threadIdx.x], s_sum[threadIdx.x]);
}

// ---- bn2 + clamp + relu + expmap0 + project : bufA (ch-last) -> out (NCHW) ---
__global__ void __launch_bounds__(256) final_kernel(const float* __restrict__ gamma,
                                                    const float* __restrict__ beta,
                                                    float* __restrict__ out) {
    __shared__ float s_aff[64];
    if (threadIdx.x < 32) {
        int c = threadIdx.x;
        const float inv = 1.0f / (float)NPIX;
        float m   = g_stats[64 + c] * inv;
        float var = fmaxf(g_stats[96 + c] * inv - m * m, 0.f);
        float is  = rsqrtf(var + 1e-5f);
        float sc  = gamma[c] * is;
        s_aff[c]      = sc;
        s_aff[32 + c] = beta[c] - m * sc;
    }
    __syncthreads();

    int q  = blockIdx.x * 64 + (threadIdx.x >> 2);
    int lq = threadIdx.x & 3;
    int c0 = lq * 8;
    int n  = q >> 16, hw = q & 65535;

    uint4 hv = ((const uint4*)g_bufA)[(size_t)q * 4 + lq];
    const uint32_t hw_[4] = {hv.x, hv.y, hv.z, hv.w};
    float u[8]; float ss = 0.f;
#pragma unroll
    for (int j2 = 0; j2 < 4; j2++) {
        float2 f = __half22float2(*(const __half2*)&hw_[j2]);
        float u0 = f.x * s_aff[c0 + 2*j2]     + s_aff[32 + c0 + 2*j2];
        float u1 = f.y * s_aff[c0 + 2*j2 + 1] + s_aff[32 + c0 + 2*j2 + 1];
        u[2*j2] = u0; u[2*j2+1] = u1;
        ss += u0 * u0 + u1 * u1;
    }
    ss += __shfl_xor_sync(0xffffffffu, ss, 1);
    ss += __shfl_xor_sync(0xffffffffu, ss, 2);
    float nrm = sqrtf(ss);
    float f1 = (nrm > R_CLAMP) ? (R_CLAMP / nrm) : 1.0f;
    float ss2 = 0.f;
#pragma unroll
    for (int j = 0; j < 8; j++) { u[j] = fmaxf(u[j] * f1, 0.f); ss2 += u[j] * u[j]; }
    ss2 += __shfl_xor_sync(0xffffffffu, ss2, 1);
    ss2 += __shfl_xor_sync(0xffffffffu, ss2, 2);
    float nrm2 = sqrtf(ss2);
    float nn  = fmaxf(nrm2, 1e-5f);
    float fac = tanhf(nn) / nn;
    float yn  = fac * nrm2;
    float pm  = fmaxf(yn, 1e-5f);
    float g2  = (pm > MAXN) ? (MAXN / pm) : 1.0f;
    float wsc = fac * g2;
    float* op = out + (size_t)n * IMG + hw;
#pragma unroll
    for (int j = 0; j < 8; j++) op[(c0 + j) << 16] = u[j] * wsc;
}

// ---------------------------------------------------------------------------
extern "C" void kernel_launch(void* const* d_in, const int* in_sizes, int n_in,
                              void* d_out, int out_size) {
    const float* x   = (const float*)d_in[0];
    const float* w1  = (const float*)d_in[1];
    const float* b1  = (const float*)d_in[2];
    const float* g1  = (const float*)d_in[3];
    const float* be1 = (const float*)d_in[4];
    const float* w2  = (const float*)d_in[5];
    const float* b2  = (const float*)d_in[6];
    const float* g2  = (const float*)d_in[7];
    const float* be2 = (const float*)d_in[8];
    float* out = (float*)d_out;

    cudaFuncSetAttribute(conv_fused_kernel<0>,
                         cudaFuncAttributeMaxDynamicSharedMemorySize, SMEM_BYTES);
    cudaFuncSetAttribute(conv_fused_kernel<1>,
                         cudaFuncAttributeMaxDynamicSharedMemorySize, SMEM_BYTES);

    dim3 cgrid(WW / 32, HH / 16, NB);   // 8 x 16 x 8 = 1024 CTAs

    zero_stats_kernel<<<1, 128>>>();                               // 1
    noop_kernel<<<1, 32>>>();                                      // 2 (ncu align)
    pack_w_kernel<<<18, 256>>>(w1, w2);                            // 3

    conv_fused_kernel<0><<<cgrid, 256, SMEM_BYTES>>>(x, b1, nullptr, nullptr); // 4
    stats_kernel<<<512, 256>>>(0, 0);                              // 5

    conv_fused_kernel<1><<<cgrid, 256, SMEM_BYTES>>>(nullptr, b2, g1, be1);    // 6 <- profiled
    stats_kernel<<<512, 256>>>(64, 1);                             // 7

    final_kernel<<<NPIX / 64, 256>>>(g2, be2, out);                // 8
}

// round 12
// speedup vs baseline: 1.0715x; 1.0262x over previous
#include <cuda_runtime.h>
#include <cuda_fp16.h>
#include <cstdint>

// ---------------------------------------------------------------------------
// HVGGBlock in tangent space; convs via mma.sync m16n8k16 fp16 implicit GEMM.
// Channel-last fp16 intermediates; logmap fused into conv1 build; BN+clamp+
// relu fused into conv2 build. Retiled: CTA = 32x8 outputs, warp = 1 pixel
// row (acc 32 regs) -> 3 CTAs/SM (24 warps) for latency hiding.
//   logmap0(project(expmap0(u))) == clampnorm(u, R), R = artanh(1-1e-4)
// ---------------------------------------------------------------------------

#define NB   8
#define CH   32
#define HH   256
#define WW   256
#define PLANE (HH*WW)
#define IMG   (CH*PLANE)
#define NPIX  (NB*PLANE)

#define R_CLAMP 4.9517188f
#define MAXN    0.9999f

__device__ __align__(16) __half g_bufB[NB*IMG];   // channel-last: [pix][32]
__device__ __align__(16) __half g_bufA[NB*IMG];   // channel-last
__device__ float g_stats[128];   // [0:32) sum1 [32:64) sq1 [64:96) sum2 [96:128) sq2
__device__ __align__(16) uint32_t g_wpack[2*18*4*32*2];  // fp16 B-frags

__global__ void noop_kernel() {}   // profiler launch-alignment

// ---- weight pack: [layer][step][Nt][lane] -> {b0,b1} fp16x2 ------------------
__global__ void __launch_bounds__(256) pack_w_kernel(const float* __restrict__ w1,
                                                     const float* __restrict__ w2) {
    int id = blockIdx.x * 256 + threadIdx.x;
    if (id >= 4608) return;
    int lay = id / 2304;
    int r   = id - lay * 2304;
    int l   = r & 31;
    int Nt  = (r >> 5) & 3;
    int st  = r >> 7;                 // 0..17
    int t   = st >> 1, s2 = st & 1;
    int tig = l & 3, gid = l >> 2;
    int co  = Nt * 8 + gid;
    int ch0 = s2 * 16 + 2 * tig;
    const float* w = lay ? w2 : w1;
    __half2 h0 = __floats2half2_rn(w[(co * CH + ch0    ) * 9 + t],
                                   w[(co * CH + ch0 + 1) * 9 + t]);
    __half2 h1 = __floats2half2_rn(w[(co * CH + ch0 + 8) * 9 + t],
                                   w[(co * CH + ch0 + 9) * 9 + t]);
    uint2* dst = (uint2*)(g_wpack + lay * 4608);
    dst[(st * 4 + Nt) * 32 + l] = make_uint2(*(const uint32_t*)&h0,
                                             *(const uint32_t*)&h1);
}

__global__ void zero_stats_kernel() {
    int t = threadIdx.x;
    if (t < 128) g_stats[t] = 0.f;
}

// ---- fused conv kernel -------------------------------------------------------
// CTA tile: 32 wide x 8 tall, halo 34x10 = 340 pixels.
// PSTRIDE*2 = 680 ≡ 8 (mod 32) -> tig-planes on disjoint bank octets.
#define PSTRIDE 340
#define SMEM_BYTES (8*PSTRIDE*8)     // 21760 dynamic

// MODE 0: src = x (fp32 NCHW), logmap, dst = g_bufB (fp16 ch-last)
// MODE 1: src = g_bufB, BN(stats[0:64])+clamp+relu, dst = g_bufA
template<int MODE>
__global__ void __launch_bounds__(256, 3)
conv_fused_kernel(const float* __restrict__ ext, const float* __restrict__ bias,
                  const float* __restrict__ gamma, const float* __restrict__ beta) {
    extern __shared__ __align__(16) uint2 s_in[];   // [8][PSTRIDE]
    __shared__ float s_aff[64];

    const int tid  = threadIdx.x;
    const int wid  = tid >> 5;
    const int lane = tid & 31;
    const int gid  = lane >> 2;
    const int tig  = lane & 3;
    const int n    = blockIdx.z;
    const int gy0  = blockIdx.y * 8;
    const int gx0  = blockIdx.x * 32;

    if (MODE == 1) {
        if (tid < 32) {
            const float inv = 1.0f / (float)NPIX;
            float m   = g_stats[tid] * inv;
            float var = fmaxf(g_stats[32 + tid] * inv - m * m, 0.f);
            float is  = rsqrtf(var + 1e-5f);
            float sc  = gamma[tid] * is;
            s_aff[tid]      = sc;
            s_aff[32 + tid] = beta[tid] - m * sc;
        }
        __syncthreads();
    }

    // ---- build: quad-cooperative (4 lanes per pixel, 8 channels per lane) ----
    const int lq = tid & 3;          // channels 8*lq .. 8*lq+7
    const int c0 = lq * 8;
    uint32_t* sw = (uint32_t*)s_in;
    const int basew = ((lq >> 1) * 4) * PSTRIDE * 2 + (lq & 1);
    for (int p0 = tid >> 2; p0 < 384; p0 += 64) {
        bool act = (p0 < 340);
        int r = p0 / 34, c = p0 - r * 34;
        int gy = gy0 + r - 1, gx = gx0 + c - 1;
        bool inb = act && ((unsigned)gy < 256u) && ((unsigned)gx < 256u);
        float v[8]; float ss = 0.f;
        if (inb) {
            if (MODE == 0) {
                const float* sp = ext + n * IMG + c0 * PLANE + gy * WW + gx;
#pragma unroll
                for (int j = 0; j < 8; j++) { v[j] = sp[j * PLANE]; ss += v[j] * v[j]; }
            } else {
                uint4 hv = ((const uint4*)g_bufB)[(n * PLANE + gy * WW + gx) * 4 + lq];
                const uint32_t hw_[4] = {hv.x, hv.y, hv.z, hv.w};
#pragma unroll
                for (int j2 = 0; j2 < 4; j2++) {
                    float2 f = __half22float2(*(const __half2*)&hw_[j2]);
                    float u0 = f.x * s_aff[c0 + 2*j2]     + s_aff[32 + c0 + 2*j2];
                    float u1 = f.y * s_aff[c0 + 2*j2 + 1] + s_aff[32 + c0 + 2*j2 + 1];
                    v[2*j2] = u0; v[2*j2+1] = u1;
                    ss += u0 * u0 + u1 * u1;
                }
            }
        } else {
#pragma unroll
            for (int j = 0; j < 8; j++) v[j] = 0.f;
        }
        ss += __shfl_xor_sync(0xffffffffu, ss, 1);
        ss += __shfl_xor_sync(0xffffffffu, ss, 2);
        float f;
        if (MODE == 0) {
            float nrm = sqrtf(ss);
            float nn  = fmaxf(nrm, 1e-5f);
            float t   = fminf(nn, 1.f - 1e-5f);
            f = 0.5f * (log1pf(t) - log1pf(-t)) / nn;              // logmap0
        } else {
            float nrm = sqrtf(ss);
            f = (nrm > R_CLAMP) ? (R_CLAMP / nrm) : 1.0f;          // clampnorm
        }
        if (act) {
#pragma unroll
            for (int j = 0; j < 4; j++) {
                float u0 = v[2*j] * f, u1 = v[2*j+1] * f;
                if (MODE == 1) { u0 = fmaxf(u0, 0.f); u1 = fmaxf(u1, 0.f); }
                __half2 h = __floats2half2_rn(u0, u1);
                sw[basew + j * (PSTRIDE * 2) + p0 * 2] = *(const uint32_t*)&h;
            }
        }
    }
    __syncthreads();

    // ---- implicit GEMM: warp owns 1 pixel row, 2 M-tiles, N=32, K=288 --------
    const uint2* wp = (const uint2*)(g_wpack + MODE * 4608);
    float acc[2][4][4];
#pragma unroll
    for (int i = 0; i < 2; i++)
#pragma unroll
        for (int Nt = 0; Nt < 4; Nt++)
#pragma unroll
            for (int j = 0; j < 4; j++) acc[i][Nt][j] = 0.f;

#pragma unroll 6
    for (int st = 0; st < 18; st++) {
        int t  = st >> 1;
        int s2 = st & 1;
        int ky = (t >= 6) ? 2 : (t >= 3 ? 1 : 0);
        int kx = t - ky * 3;

        uint2 b[4];
#pragma unroll
        for (int Nt = 0; Nt < 4; Nt++) b[Nt] = wp[(st * 4 + Nt) * 32 + lane];

        int pixbase = (s2 * 4 + tig) * PSTRIDE + (wid + ky) * 34 + kx + gid;
#pragma unroll
        for (int i = 0; i < 2; i++) {
            int px = pixbase + i * 16;
            uint2 A0 = s_in[px];
            uint2 A1 = s_in[px + 8];
#pragma unroll
            for (int Nt = 0; Nt < 4; Nt++) {
                asm volatile(
                    "mma.sync.aligned.m16n8k16.row.col.f32.f16.f16.f32 "
                    "{%0,%1,%2,%3}, {%4,%5,%6,%7}, {%8,%9}, {%0,%1,%2,%3};"
                    : "+f"(acc[i][Nt][0]), "+f"(acc[i][Nt][1]),
                      "+f"(acc[i][Nt][2]), "+f"(acc[i][Nt][3])
                    : "r"(A0.x), "r"(A1.x), "r"(A0.y), "r"(A1.y),
                      "r"(b[Nt].x), "r"(b[Nt].y));
            }
        }
    }

    // ---- epilogue: bias + per-pixel clampnorm + half2 channel-last store -----
    float2 bs[4];
#pragma unroll
    for (int Nt = 0; Nt < 4; Nt++)
        bs[Nt] = *(const float2*)(bias + Nt * 8 + 2 * tig);

    uint32_t* o2 = (uint32_t*)(MODE == 0 ? g_bufB : g_bufA) + (size_t)n * PLANE * 16;
#pragma unroll
    for (int i = 0; i < 2; i++) {
        int xlA = i * 16 + gid;
        float vA[8], vB[8];
        float ssA = 0.f, ssB = 0.f;
#pragma unroll
        for (int Nt = 0; Nt < 4; Nt++) {
            float a0 = acc[i][Nt][0] + bs[Nt].x;
            float a1 = acc[i][Nt][1] + bs[Nt].y;
            float b0 = acc[i][Nt][2] + bs[Nt].x;
            float b1 = acc[i][Nt][3] + bs[Nt].y;
            vA[2 * Nt] = a0; vA[2 * Nt + 1] = a1;
            vB[2 * Nt] = b0; vB[2 * Nt + 1] = b1;
            ssA += a0 * a0 + a1 * a1;
            ssB += b0 * b0 + b1 * b1;
        }
        ssA += __shfl_xor_sync(0xffffffffu, ssA, 1);
        ssA += __shfl_xor_sync(0xffffffffu, ssA, 2);
        ssB += __shfl_xor_sync(0xffffffffu, ssB, 1);
        ssB += __shfl_xor_sync(0xffffffffu, ssB, 2);
        float nA = sqrtf(ssA), nB = sqrtf(ssB);
        float fA = (nA > R_CLAMP) ? (R_CLAMP / nA) : 1.0f;
        float fB = (nB > R_CLAMP) ? (R_CLAMP / nB) : 1.0f;
        int pixA = (gy0 + wid) * WW + gx0 + xlA;
        int pixB = pixA + 8;
#pragma unroll
        for (int Nt = 0; Nt < 4; Nt++) {
            int cp = Nt * 4 + tig;
            __half2 hA = __floats2half2_rn(vA[2 * Nt] * fA, vA[2 * Nt + 1] * fA);
            __half2 hB = __floats2half2_rn(vB[2 * Nt] * fB, vB[2 * Nt + 1] * fB);
            o2[pixA * 16 + cp] = *(const uint32_t*)&hA;
            o2[pixB * 16 + cp] = *(const uint32_t*)&hB;
        }
    }
}

// ---- per-channel sum/sumsq over channel-last fp16 buffer ---------------------
__global__ void __launch_bounds__(256) stats_kernel(int statOff, int which) {
    const uint32_t* b2 = (const uint32_t*)(which ? g_bufA : g_bufB);
    const int cpair = threadIdx.x & 15;
    const int row   = threadIdx.x >> 4;
    const int base  = blockIdx.x * 1024;
    float s0 = 0.f, s1 = 0.f, q0 = 0.f, q1 = 0.f;
    for (int pp = row; pp < 1024; pp += 16) {
        uint32_t h = b2[(size_t)(base + pp) * 16 + cpair];
        float2 f = __half22float2(*(const __half2*)&h);
        s0 += f.x; q0 += f.x * f.x;
        s1 += f.y; q1 += f.y * f.y;
    }
    s0 += __shfl_xor_sync(0xffffffffu, s0, 16);
    s1 += __shfl_xor_sync(0xffffffffu, s1, 16);
    q0 += __shfl_xor_sync(0xffffffffu, q0, 16);
    q1 += __shfl_xor_sync(0xffffffffu, q1, 16);
    __shared__ float s_sum[64];
    if (threadIdx.x < 64) s_sum[threadIdx.x] = 0.f;
    __syncthreads();
    if ((threadIdx.x & 31) < 16) {
        atomicAdd(&s_sum[2 * cpair],      s0);
        atomicAdd(&s_sum[2 * cpair + 1],  s1);
        atomicAdd(&s_sum[32 + 2 * cpair],     q0);
        atomicAdd(&s_sum[32 + 2 * cpair + 1], q1);
    }
    __syncthreads();
    if (threadIdx.x < 64) atomicAdd(&g_stats[statOff + threadIdx.x], s_sum[threadIdx.x]);
}

// ---- bn2 + clamp + relu + expmap0 + project : bufA (ch-last) -> out (NCHW) ---
__global__ void __launch_bounds__(256) final_kernel(const float* __restrict__ gamma,
                                                    const float* __restrict__ beta,
                                                    float* __restrict__ out) {
    __shared__ float s_aff[64];
    if (threadIdx.x < 32) {
        int c = threadIdx.x;
        const float inv = 1.0f / (float)NPIX;
        float m   = g_stats[64 + c] * inv;
        float var = fmaxf(g_stats[96 + c] * inv - m * m, 0.f);
        float is  = rsqrtf(var + 1e-5f);
        float sc  = gamma[c] * is;
        s_aff[c]      = sc;
        s_aff[32 + c] = beta[c] - m * sc;
    }
    __syncthreads();

    int q  = blockIdx.x * 64 + (threadIdx.x >> 2);
    int lq = threadIdx.x & 3;
    int c0 = lq * 8;
    int n  = q >> 16, hw = q & 65535;

    uint4 hv = ((const uint4*)g_bufA)[(size_t)q * 4 + lq];
    const uint32_t hw_[4] = {hv.x, hv.y, hv.z, hv.w};
    float u[8]; float ss = 0.f;
#pragma unroll
    for (int j2 = 0; j2 < 4; j2++) {
        float2 f = __half22float2(*(const __half2*)&hw_[j2]);
        float u0 = f.x * s_aff[c0 + 2*j2]     + s_aff[32 + c0 + 2*j2];
        float u1 = f.y * s_aff[c0 + 2*j2 + 1] + s_aff[32 + c0 + 2*j2 + 1];
        u[2*j2] = u0; u[2*j2+1] = u1;
        ss += u0 * u0 + u1 * u1;
    }
    ss += __shfl_xor_sync(0xffffffffu, ss, 1);
    ss += __shfl_xor_sync(0xffffffffu, ss, 2);
    float nrm = sqrtf(ss);
    float f1 = (nrm > R_CLAMP) ? (R_CLAMP / nrm) : 1.0f;
    float ss2 = 0.f;
#pragma unroll
    for (int j = 0; j < 8; j++) { u[j] = fmaxf(u[j] * f1, 0.f); ss2 += u[j] * u[j]; }
    ss2 += __shfl_xor_sync(0xffffffffu, ss2, 1);
    ss2 += __shfl_xor_sync(0xffffffffu, ss2, 2);
    float nrm2 = sqrtf(ss2);
    float nn  = fmaxf(nrm2, 1e-5f);
    float fac = tanhf(nn) / nn;
    float yn  = fac * nrm2;
    float pm  = fmaxf(yn, 1e-5f);
    float g2  = (pm > MAXN) ? (MAXN / pm) : 1.0f;
    float wsc = fac * g2;
    float* op = out + (size_t)n * IMG + hw;
#pragma unroll
    for (int j = 0; j < 8; j++) op[(c0 + j) << 16] = u[j] * wsc;
}

// ---------------------------------------------------------------------------
extern "C" void kernel_launch(void* const* d_in, const int* in_sizes, int n_in,
                              void* d_out, int out_size) {
    const float* x   = (const float*)d_in[0];
    const float* w1  = (const float*)d_in[1];
    const float* b1  = (const float*)d_in[2];
    const float* g1  = (const float*)d_in[3];
    const float* be1 = (const float*)d_in[4];
    const float* w2  = (const float*)d_in[5];
    const float* b2  = (const float*)d_in[6];
    const float* g2  = (const float*)d_in[7];
    const float* be2 = (const float*)d_in[8];
    float* out = (float*)d_out;

    cudaFuncSetAttribute(conv_fused_kernel<0>,
                         cudaFuncAttributeMaxDynamicSharedMemorySize, SMEM_BYTES);
    cudaFuncSetAttribute(conv_fused_kernel<1>,
                         cudaFuncAttributeMaxDynamicSharedMemorySize, SMEM_BYTES);

    dim3 cgrid(WW / 32, HH / 8, NB);   // 8 x 32 x 8 = 2048 CTAs

    zero_stats_kernel<<<1, 128>>>();                               // 1
    noop_kernel<<<1, 32>>>();                                      // 2 (ncu align)
    pack_w_kernel<<<18, 256>>>(w1, w2);                            // 3

    conv_fused_kernel<0><<<cgrid, 256, SMEM_BYTES>>>(x, b1, nullptr, nullptr); // 4
    stats_kernel<<<512, 256>>>(0, 0);                              // 5

    conv_fused_kernel<1><<<cgrid, 256, SMEM_BYTES>>>(nullptr, b2, g1, be1);    // 6 <- profiled
    stats_kernel<<<512, 256>>>(64, 1);                             // 7

    final_kernel<<<NPIX / 64, 256>>>(g2, be2, out);                // 8
}

// round 13
// speedup vs baseline: 1.1296x; 1.0543x over previous
#include <cuda_runtime.h>
#include <cuda_fp16.h>
#include <cstdint>

// ---------------------------------------------------------------------------
// HVGGBlock in tangent space; convs via mma.sync m16n8k16 fp16 implicit GEMM.
// A tile in smem as [s2-half][pixel][16ch], 48B pixel slots (conflict-free
// ldmatrix.x4); B fragments pointer-walked from global; K loop fully unrolled.
// CTA = 32x8 outputs, warp = 1 pixel row, 3 CTAs/SM.
//   logmap0(project(expmap0(u))) == clampnorm(u, R), R = artanh(1-1e-4)
// ---------------------------------------------------------------------------

#define NB   8
#define CH   32
#define HH   256
#define WW   256
#define PLANE (HH*WW)
#define IMG   (CH*PLANE)
#define NPIX  (NB*PLANE)

#define R_CLAMP 4.9517188f
#define MAXN    0.9999f

__device__ __align__(16) __half g_bufB[NB*IMG];   // channel-last: [pix][32]
__device__ __align__(16) __half g_bufA[NB*IMG];   // channel-last
__device__ float g_stats[128];   // [0:32) sum1 [32:64) sq1 [64:96) sum2 [96:128) sq2
__device__ __align__(16) uint32_t g_wpack[2*18*4*32*2];  // fp16 B-frags

__global__ void noop_kernel() {}   // profiler launch-alignment

__device__ __forceinline__ uint32_t smem_u32_of(const void* p) {
    uint32_t a;
    asm("{ .reg .u64 t; cvta.to.shared.u64 t, %1; cvt.u32.u64 %0, t; }" : "=r"(a) : "l"(p));
    return a;
}

#define LDSM_X4(r0, r1, r2, r3, addr) \
    asm volatile("ldmatrix.sync.aligned.m8n8.x4.shared.b16 {%0,%1,%2,%3}, [%4];" \
        : "=r"(r0), "=r"(r1), "=r"(r2), "=r"(r3) : "r"(addr))

// ---- weight pack: [layer][step][Nt][lane] -> {b0,b1} fp16x2 ------------------
__global__ void __launch_bounds__(256) pack_w_kernel(const float* __restrict__ w1,
                                                     const float* __restrict__ w2) {
    int id = blockIdx.x * 256 + threadIdx.x;
    if (id >= 4608) return;
    int lay = id / 2304;
    int r   = id - lay * 2304;
    int l   = r & 31;
    int Nt  = (r >> 5) & 3;
    int st  = r >> 7;                 // 0..17
    int t   = st >> 1, s2 = st & 1;
    int tig = l & 3, gid = l >> 2;
    int co  = Nt * 8 + gid;
    int ch0 = s2 * 16 + 2 * tig;
    const float* w = lay ? w2 : w1;
    __half2 h0 = __floats2half2_rn(w[(co * CH + ch0    ) * 9 + t],
                                   w[(co * CH + ch0 + 1) * 9 + t]);
    __half2 h1 = __floats2half2_rn(w[(co * CH + ch0 + 8) * 9 + t],
                                   w[(co * CH + ch0 + 9) * 9 + t]);
    uint2* dst = (uint2*)(g_wpack + lay * 4608);
    dst[(st * 4 + Nt) * 32 + l] = make_uint2(*(const uint32_t*)&h0,
                                             *(const uint32_t*)&h1);
}

__global__ void zero_stats_kernel() {
    int t = threadIdx.x;
    if (t < 128) g_stats[t] = 0.f;
}

// ---- fused conv kernel -------------------------------------------------------
// CTA tile: 32 wide x 8 tall, halo 34x10 = 340 pixels.
// smem: 2 s2-halves x 340 pixels x 48B slot (32B data: k0-7 @0, k8-15 @16).
#define SLOT    48
#define S2OFF   (340*SLOT)            // 16320
#define SMEM_BYTES (2*S2OFF)          // 32640 dynamic

// MODE 0: src = x (fp32 NCHW), logmap, dst = g_bufB (fp16 ch-last)
// MODE 1: src = g_bufB, BN(stats[0:64])+clamp+relu, dst = g_bufA
template<int MODE>
__global__ void __launch_bounds__(256, 3)
conv_fused_kernel(const float* __restrict__ ext, const float* __restrict__ bias,
                  const float* __restrict__ gamma, const float* __restrict__ beta) {
    extern __shared__ __align__(16) char smem[];
    __shared__ float s_aff[64];

    const int tid  = threadIdx.x;
    const int wid  = tid >> 5;
    const int lane = tid & 31;
    const int gid  = lane >> 2;
    const int tig  = lane & 3;
    const int n    = blockIdx.z;
    const int gy0  = blockIdx.y * 8;
    const int gx0  = blockIdx.x * 32;

    if (MODE == 1) {
        if (tid < 32) {
            const float inv = 1.0f / (float)NPIX;
            float m   = g_stats[tid] * inv;
            float var = fmaxf(g_stats[32 + tid] * inv - m * m, 0.f);
            float is  = rsqrtf(var + 1e-5f);
            float sc  = gamma[tid] * is;
            s_aff[tid]      = sc;
            s_aff[32 + tid] = beta[tid] - m * sc;
        }
        __syncthreads();
    }

    // ---- build: quad-cooperative; lane's 8 channels are one 16B STS.128 ------
    const int lq = tid & 3;          // channels 8*lq .. 8*lq+7
    const int c0 = lq * 8;
    char* wr = smem + (lq >> 1) * S2OFF + (lq & 1) * 16;
    for (int p0 = tid >> 2; p0 < 384; p0 += 64) {
        bool act = (p0 < 340);
        int r = p0 / 34, c = p0 - r * 34;
        int gy = gy0 + r - 1, gx = gx0 + c - 1;
        bool inb = act && ((unsigned)gy < 256u) && ((unsigned)gx < 256u);
        float v[8]; float ss = 0.f;
        if (inb) {
            if (MODE == 0) {
                const float* sp = ext + n * IMG + c0 * PLANE + gy * WW + gx;
#pragma unroll
                for (int j = 0; j < 8; j++) { v[j] = sp[j * PLANE]; ss += v[j] * v[j]; }
            } else {
                uint4 hv = ((const uint4*)g_bufB)[(n * PLANE + gy * WW + gx) * 4 + lq];
                const uint32_t hw_[4] = {hv.x, hv.y, hv.z, hv.w};
#pragma unroll
                for (int j2 = 0; j2 < 4; j2++) {
                    float2 f = __half22float2(*(const __half2*)&hw_[j2]);
                    float u0 = f.x * s_aff[c0 + 2*j2]     + s_aff[32 + c0 + 2*j2];
                    float u1 = f.y * s_aff[c0 + 2*j2 + 1] + s_aff[32 + c0 + 2*j2 + 1];
                    v[2*j2] = u0; v[2*j2+1] = u1;
                    ss += u0 * u0 + u1 * u1;
                }
            }
        } else {
#pragma unroll
            for (int j = 0; j < 8; j++) v[j] = 0.f;
        }
        ss += __shfl_xor_sync(0xffffffffu, ss, 1);
        ss += __shfl_xor_sync(0xffffffffu, ss, 2);
        float f;
        if (MODE == 0) {
            float nrm = sqrtf(ss);
            float nn  = fmaxf(nrm, 1e-5f);
            float t   = fminf(nn, 1.f - 1e-5f);
            f = 0.5f * (log1pf(t) - log1pf(-t)) / nn;              // logmap0
        } else {
            float nrm = sqrtf(ss);
            f = (nrm > R_CLAMP) ? (R_CLAMP / nrm) : 1.0f;          // clampnorm
        }
        if (act) {
            uint32_t hh[4];
#pragma unroll
            for (int j = 0; j < 4; j++) {
                float u0 = v[2*j] * f, u1 = v[2*j+1] * f;
                if (MODE == 1) { u0 = fmaxf(u0, 0.f); u1 = fmaxf(u1, 0.f); }
                __half2 h = __floats2half2_rn(u0, u1);
                hh[j] = *(const uint32_t*)&h;
            }
            *(uint4*)(wr + p0 * SLOT) = make_uint4(hh[0], hh[1], hh[2], hh[3]);
        }
    }
    __syncthreads();

    // ---- implicit GEMM: warp owns 1 pixel row, 2 M-tiles, N=32, K=288 --------
    const uint2* wp = ((const uint2*)(g_wpack + MODE * 4608)) + lane;
    float acc[2][4][4];
#pragma unroll
    for (int i = 0; i < 2; i++)
#pragma unroll
        for (int Nt = 0; Nt < 4; Nt++)
#pragma unroll
            for (int j = 0; j < 4; j++) acc[i][Nt][j] = 0.f;

    // per-lane constant part of the ldmatrix row address
    const uint32_t abase = smem_u32_of(smem)
                         + (uint32_t)((lane & 15) * SLOT + (lane >> 4) * 16)
                         + (uint32_t)(wid * 34 * SLOT);

#pragma unroll
    for (int st = 0; st < 18; st++) {
        const int t  = st >> 1;
        const int s2 = st & 1;
        const int ky = (t >= 6) ? 2 : (t >= 3 ? 1 : 0);
        const int kx = t - ky * 3;

        uint2 b0 = wp[0], b1 = wp[32], b2 = wp[64], b3 = wp[96];
        wp += 128;

        const uint32_t rowaddr = abase + (uint32_t)(s2 * S2OFF + (ky * 34 + kx) * SLOT);
#pragma unroll
        for (int i = 0; i < 2; i++) {
            uint32_t a0, a1, a2, a3;
            LDSM_X4(a0, a1, a2, a3, rowaddr + (uint32_t)(i * 16 * SLOT));
#define MMA_NT(BB, NT)                                                          \
            asm volatile(                                                       \
                "mma.sync.aligned.m16n8k16.row.col.f32.f16.f16.f32 "            \
                "{%0,%1,%2,%3}, {%4,%5,%6,%7}, {%8,%9}, {%0,%1,%2,%3};"         \
                : "+f"(acc[i][NT][0]), "+f"(acc[i][NT][1]),                     \
                  "+f"(acc[i][NT][2]), "+f"(acc[i][NT][3])                      \
                : "r"(a0), "r"(a1), "r"(a2), "r"(a3),                           \
                  "r"(BB.x), "r"(BB.y))
            MMA_NT(b0, 0); MMA_NT(b1, 1); MMA_NT(b2, 2); MMA_NT(b3, 3);
#undef MMA_NT
        }
    }

    // ---- epilogue: bias + per-pixel clampnorm + half2 channel-last store -----
    float2 bs[4];
#pragma unroll
    for (int Nt = 0; Nt < 4; Nt++)
        bs[Nt] = *(const float2*)(bias + Nt * 8 + 2 * tig);

    uint32_t* o2 = (uint32_t*)(MODE == 0 ? g_bufB : g_bufA) + (size_t)n * PLANE * 16;
#pragma unroll
    for (int i = 0; i < 2; i++) {
        int xlA = i * 16 + gid;
        float vA[8], vB[8];
        float ssA = 0.f, ssB = 0.f;
#pragma unroll
        for (int Nt = 0; Nt < 4; Nt++) {
            float a0 = acc[i][Nt][0] + bs[Nt].x;
            float a1 = acc[i][Nt][1] + bs[Nt].y;
            float b0 = acc[i][Nt][2] + bs[Nt].x;
            float b1 = acc[i][Nt][3] + bs[Nt].y;
            vA[2 * Nt] = a0; vA[2 * Nt + 1] = a1;
            vB[2 * Nt] = b0; vB[2 * Nt + 1] = b1;
            ssA += a0 * a0 + a1 * a1;
            ssB += b0 * b0 + b1 * b1;
        }
        ssA += __shfl_xor_sync(0xffffffffu, ssA, 1);
        ssA += __shfl_xor_sync(0xffffffffu, ssA, 2);
        ssB += __shfl_xor_sync(0xffffffffu, ssB, 1);
        ssB += __shfl_xor_sync(0xffffffffu, ssB, 2);
        float nA = sqrtf(ssA), nB = sqrtf(ssB);
        float fA = (nA > R_CLAMP) ? (R_CLAMP / nA) : 1.0f;
        float fB = (nB > R_CLAMP) ? (R_CLAMP / nB) : 1.0f;
        int pixA = (gy0 + wid) * WW + gx0 + xlA;
        int pixB = pixA + 8;
#pragma unroll
        for (int Nt = 0; Nt < 4; Nt++) {
            int cp = Nt * 4 + tig;
            __half2 hA = __floats2half2_rn(vA[2 * Nt] * fA, vA[2 * Nt + 1] * fA);
            __half2 hB = __floats2half2_rn(vB[2 * Nt] * fB, vB[2 * Nt + 1] * fB);
            o2[pixA * 16 + cp] = *(const uint32_t*)&hA;
            o2[pixB * 16 + cp] = *(const uint32_t*)&hB;
        }
    }
}

// ---- per-channel sum/sumsq over channel-last fp16 buffer (uint4 loads) -------
__global__ void __launch_bounds__(256) stats_kernel(int statOff, int which) {
    const uint4* b4 = (const uint4*)(which ? g_bufA : g_bufB);
    const int q  = threadIdx.x & 3;      // channel group 8q..8q+7
    const int pr = threadIdx.x >> 2;     // 0..63
    const size_t base = (size_t)blockIdx.x * 1024;
    float s[8], sq[8];
#pragma unroll
    for (int j = 0; j < 8; j++) { s[j] = 0.f; sq[j] = 0.f; }
    for (int pp = pr; pp < 1024; pp += 64) {
        uint4 v = b4[(base + pp) * 4 + q];
        const uint32_t w_[4] = {v.x, v.y, v.z, v.w};
#pragma unroll
        for (int j2 = 0; j2 < 4; j2++) {
            float2 f = __half22float2(*(const __half2*)&w_[j2]);
            s[2*j2]   += f.x;  sq[2*j2]   += f.x * f.x;
            s[2*j2+1] += f.y;  sq[2*j2+1] += f.y * f.y;
        }
    }
    // reduce over the 8 lanes sharing q (gid 0..7)
#pragma unroll
    for (int j = 0; j < 8; j++) {
#pragma unroll
        for (int o = 4; o <= 16; o <<= 1) {
            s[j]  += __shfl_xor_sync(0xffffffffu, s[j],  o);
            sq[j] += __shfl_xor_sync(0xffffffffu, sq[j], o);
        }
    }
    __shared__ float ssum[64];
    if (threadIdx.x < 64) ssum[threadIdx.x] = 0.f;
    __syncthreads();
    if ((threadIdx.x & 31) < 4) {
#pragma unroll
        for (int j = 0; j < 8; j++) {
            atomicAdd(&ssum[q * 8 + j],      s[j]);
            atomicAdd(&ssum[32 + q * 8 + j], sq[j]);
        }
    }
    __syncthreads();
    if (threadIdx.x < 64) atomicAdd(&g_stats[statOff + threadIdx.x], ssum[threadIdx.x]);
}

// ---- bn2 + clamp + relu + expmap0 + project : bufA (ch-last) -> out (NCHW) ---
__global__ void __launch_bounds__(256) final_kernel(const float* __restrict__ gamma,
                                                    const float* __restrict__ beta,
                                                    float* __restrict__ out) {
    __shared__ float s_aff[64];
    if (threadIdx.x < 32) {
        int c = threadIdx.x;
        const float inv = 1.0f / (float)NPIX;
        float m   = g_stats[64 + c] * inv;
        float var = fmaxf(g_stats[96 + c] * inv - m * m, 0.f);
        float is  = rsqrtf(var + 1e-5f);
        float sc  = gamma[c] * is;
        s_aff[c]      = sc;
        s_aff[32 + c] = beta[c] - m * sc;
    }
    __syncthreads();

    int q  = blockIdx.x * 64 + (threadIdx.x >> 2);
    int lq = threadIdx.x & 3;
    int c0 = lq * 8;
    int n  = q >> 16, hw = q & 65535;

    uint4 hv = ((const uint4*)g_bufA)[(size_t)q * 4 + lq];
    const uint32_t hw_[4] = {hv.x, hv.y, hv.z, hv.w};
    float u[8]; float ss = 0.f;
#pragma unroll
    for (int j2 = 0; j2 < 4; j2++) {
        float2 f = __half22float2(*(const __half2*)&hw_[j2]);
        float u0 = f.x * s_aff[c0 + 2*j2]     + s_aff[32 + c0 + 2*j2];
        float u1 = f.y * s_aff[c0 + 2*j2 + 1] + s_aff[32 + c0 + 2*j2 + 1];
        u[2*j2] = u0; u[2*j2+1] = u1;
        ss += u0 * u0 + u1 * u1;
    }
    ss += __shfl_xor_sync(0xffffffffu, ss, 1);
    ss += __shfl_xor_sync(0xffffffffu, ss, 2);
    float nrm = sqrtf(ss);
    float f1 = (nrm > R_CLAMP) ? (R_CLAMP / nrm) : 1.0f;
    float ss2 = 0.f;
#pragma unroll
    for (int j = 0; j < 8; j++) { u[j] = fmaxf(u[j] * f1, 0.f); ss2 += u[j] * u[j]; }
    ss2 += __shfl_xor_sync(0xffffffffu, ss2, 1);
    ss2 += __shfl_xor_sync(0xffffffffu, ss2, 2);
    float nrm2 = sqrtf(ss2);
    float nn  = fmaxf(nrm2, 1e-5f);
    float fac = tanhf(nn) / nn;
    float yn  = fac * nrm2;
    float pm  = fmaxf(yn, 1e-5f);
    float g2  = (pm > MAXN) ? (MAXN / pm) : 1.0f;
    float wsc = fac * g2;
    float* op = out + (size_t)n * IMG + hw;
#pragma unroll
    for (int j = 0; j < 8; j++) op[(c0 + j) << 16] = u[j] * wsc;
}

// ---------------------------------------------------------------------------
extern "C" void kernel_launch(void* const* d_in, const int* in_sizes, int n_in,
                              void* d_out, int out_size) {
    const float* x   = (const float*)d_in[0];
    const float* w1  = (const float*)d_in[1];
    const float* b1  = (const float*)d_in[2];
    const float* g1  = (const float*)d_in[3];
    const float* be1 = (const float*)d_in[4];
    const float* w2  = (const float*)d_in[5];
    const float* b2  = (const float*)d_in[6];
    const float* g2  = (const float*)d_in[7];
    const float* be2 = (const float*)d_in[8];
    float* out = (float*)d_out;

    cudaFuncSetAttribute(conv_fused_kernel<0>,
                         cudaFuncAttributeMaxDynamicSharedMemorySize, SMEM_BYTES);
    cudaFuncSetAttribute(conv_fused_kernel<1>,
                         cudaFuncAttributeMaxDynamicSharedMemorySize, SMEM_BYTES);

    dim3 cgrid(WW / 32, HH / 8, NB);   // 8 x 32 x 8 = 2048 CTAs

    zero_stats_kernel<<<1, 128>>>();                               // 1
    noop_kernel<<<1, 32>>>();                                      // 2 (ncu align)
    pack_w_kernel<<<18, 256>>>(w1, w2);                            // 3

    conv_fused_kernel<0><<<cgrid, 256, SMEM_BYTES>>>(x, b1, nullptr, nullptr); // 4
    stats_kernel<<<512, 256>>>(0, 0);                              // 5

    conv_fused_kernel<1><<<cgrid, 256, SMEM_BYTES>>>(nullptr, b2, g1, be1);    // 6
    stats_kernel<<<512, 256>>>(64, 1);                             // 7

    final_kernel<<<NPIX / 64, 256>>>(g2, be2, out);                // 8
}

// round 14
// speedup vs baseline: 1.1532x; 1.0209x over previous
#include <cuda_runtime.h>
#include <cuda_fp16.h>
#include <cstdint>

// ---------------------------------------------------------------------------
// HVGGBlock in tangent space; convs via mma.sync m16n8k16 fp16 implicit GEMM.
// A tile in smem as [s2-half][pixel][16ch], 48B slots (conflict-free
// ldmatrix.x4). Weight pack permutes couts (cout = 8*(col>>1)+2*Nt+(col&1))
// so each epilogue lane owns a contiguous 16B channel chunk -> STG.128,
// fully coalesced, buffer layout still canonical channel-last.
// CTA = 32x8 outputs, warp = 1 pixel row, 3 CTAs/SM.
//   logmap0(project(expmap0(u))) == clampnorm(u, R), R = artanh(1-1e-4)
// ---------------------------------------------------------------------------

#define NB   8
#define CH   32
#define HH   256
#define WW   256
#define PLANE (HH*WW)
#define IMG   (CH*PLANE)
#define NPIX  (NB*PLANE)

#define R_CLAMP 4.9517188f
#define MAXN    0.9999f

__device__ __align__(16) __half g_bufB[NB*IMG];   // channel-last: [pix][32]
__device__ __align__(16) __half g_bufA[NB*IMG];   // channel-last
__device__ float g_stats[128];   // [0:32) sum1 [32:64) sq1 [64:96) sum2 [96:128) sq2
__device__ __align__(16) uint32_t g_wpack[2*18*4*32*2];  // fp16 B-frags

__global__ void noop_kernel() {}   // profiler launch-alignment

__device__ __forceinline__ uint32_t smem_u32_of(const void* p) {
    uint32_t a;
    asm("{ .reg .u64 t; cvta.to.shared.u64 t, %1; cvt.u32.u64 %0, t; }" : "=r"(a) : "l"(p));
    return a;
}

#define LDSM_X4(r0, r1, r2, r3, addr) \
    asm volatile("ldmatrix.sync.aligned.m8n8.x4.shared.b16 {%0,%1,%2,%3}, [%4];" \
        : "=r"(r0), "=r"(r1), "=r"(r2), "=r"(r3) : "r"(addr))

// ---- weight pack: [layer][step][Nt][lane] -> {b0,b1} fp16x2 ------------------
// cout permutation: column gd of N-tile Nt -> cout = 8*(gd>>1) + 2*Nt + (gd&1)
// => epilogue lane tig owns couts 8*tig..8*tig+7 (contiguous STG.128).
__global__ void __launch_bounds__(256) pack_w_kernel(const float* __restrict__ w1,
                                                     const float* __restrict__ w2) {
    int id = blockIdx.x * 256 + threadIdx.x;
    if (id >= 4608) return;
    int lay = id / 2304;
    int r   = id - lay * 2304;
    int l   = r & 31;
    int Nt  = (r >> 5) & 3;
    int st  = r >> 7;                 // 0..17
    int t   = st >> 1, s2 = st & 1;
    int tig = l & 3, gd = l >> 2;
    int co  = 8 * (gd >> 1) + 2 * Nt + (gd & 1);   // permuted cout
    int ch0 = s2 * 16 + 2 * tig;
    const float* w = lay ? w2 : w1;
    __half2 h0 = __floats2half2_rn(w[(co * CH + ch0    ) * 9 + t],
                                   w[(co * CH + ch0 + 1) * 9 + t]);
    __half2 h1 = __floats2half2_rn(w[(co * CH + ch0 + 8) * 9 + t],
                                   w[(co * CH + ch0 + 9) * 9 + t]);
    uint2* dst = (uint2*)(g_wpack + lay * 4608);
    dst[(st * 4 + Nt) * 32 + l] = make_uint2(*(const uint32_t*)&h0,
                                             *(const uint32_t*)&h1);
}

__global__ void zero_stats_kernel() {
    int t = threadIdx.x;
    if (t < 128) g_stats[t] = 0.f;
}

// ---- fused conv kernel -------------------------------------------------------
#define SLOT    48
#define S2OFF   (340*SLOT)            // 16320
#define SMEM_BYTES (2*S2OFF)          // 32640 dynamic

// MODE 0: src = x (fp32 NCHW), logmap, dst = g_bufB (fp16 ch-last)
// MODE 1: src = g_bufB, BN(stats[0:64])+clamp+relu, dst = g_bufA
template<int MODE>
__global__ void __launch_bounds__(256, 3)
conv_fused_kernel(const float* __restrict__ ext, const float* __restrict__ bias,
                  const float* __restrict__ gamma, const float* __restrict__ beta) {
    extern __shared__ __align__(16) char smem[];
    __shared__ float s_aff[64];

    const int tid  = threadIdx.x;
    const int wid  = tid >> 5;
    const int lane = tid & 31;
    const int gid  = lane >> 2;
    const int tig  = lane & 3;
    const int n    = blockIdx.z;
    const int gy0  = blockIdx.y * 8;
    const int gx0  = blockIdx.x * 32;

    if (MODE == 1) {
        if (tid < 32) {
            const float inv = 1.0f / (float)NPIX;
            float m   = g_stats[tid] * inv;
            float var = fmaxf(g_stats[32 + tid] * inv - m * m, 0.f);
            float is  = rsqrtf(var + 1e-5f);
            float sc  = gamma[tid] * is;
            s_aff[tid]      = sc;
            s_aff[32 + tid] = beta[tid] - m * sc;
        }
        __syncthreads();
    }

    // ---- build: quad-cooperative; lane's 8 channels are one 16B STS.128 ------
    const int lq = tid & 3;          // channels 8*lq .. 8*lq+7
    const int c0 = lq * 8;
    char* wr = smem + (lq >> 1) * S2OFF + (lq & 1) * 16;
    for (int p0 = tid >> 2; p0 < 384; p0 += 64) {
        bool act = (p0 < 340);
        int r = p0 / 34, c = p0 - r * 34;
        int gy = gy0 + r - 1, gx = gx0 + c - 1;
        bool inb = act && ((unsigned)gy < 256u) && ((unsigned)gx < 256u);
        float v[8]; float ss = 0.f;
        if (inb) {
            if (MODE == 0) {
                const float* sp = ext + n * IMG + c0 * PLANE + gy * WW + gx;
#pragma unroll
                for (int j = 0; j < 8; j++) { v[j] = sp[j * PLANE]; ss += v[j] * v[j]; }
            } else {
                uint4 hv = ((const uint4*)g_bufB)[(n * PLANE + gy * WW + gx) * 4 + lq];
                const uint32_t hw_[4] = {hv.x, hv.y, hv.z, hv.w};
#pragma unroll
                for (int j2 = 0; j2 < 4; j2++) {
                    float2 f = __half22float2(*(const __half2*)&hw_[j2]);
                    float u0 = f.x * s_aff[c0 + 2*j2]     + s_aff[32 + c0 + 2*j2];
                    float u1 = f.y * s_aff[c0 + 2*j2 + 1] + s_aff[32 + c0 + 2*j2 + 1];
                    v[2*j2] = u0; v[2*j2+1] = u1;
                    ss += u0 * u0 + u1 * u1;
                }
            }
        } else {
#pragma unroll
            for (int j = 0; j < 8; j++) v[j] = 0.f;
        }
        ss += __shfl_xor_sync(0xffffffffu, ss, 1);
        ss += __shfl_xor_sync(0xffffffffu, ss, 2);
        float f;
        if (MODE == 0) {
            float nrm = sqrtf(ss);
            float nn  = fmaxf(nrm, 1e-5f);
            float t   = fminf(nn, 1.f - 1e-5f);
            f = 0.5f * (log1pf(t) - log1pf(-t)) / nn;              // logmap0
        } else {
            float nrm = sqrtf(ss);
            f = (nrm > R_CLAMP) ? (R_CLAMP / nrm) : 1.0f;          // clampnorm
        }
        if (act) {
            uint32_t hh[4];
#pragma unroll
            for (int j = 0; j < 4; j++) {
                float u0 = v[2*j] * f, u1 = v[2*j+1] * f;
                if (MODE == 1) { u0 = fmaxf(u0, 0.f); u1 = fmaxf(u1, 0.f); }
                __half2 h = __floats2half2_rn(u0, u1);
                hh[j] = *(const uint32_t*)&h;
            }
            *(uint4*)(wr + p0 * SLOT) = make_uint4(hh[0], hh[1], hh[2], hh[3]);
        }
    }
    __syncthreads();

    // ---- implicit GEMM: warp owns 1 pixel row, 2 M-tiles, N=32, K=288 --------
    const uint2* wp = ((const uint2*)(g_wpack + MODE * 4608)) + lane;
    float acc[2][4][4];
#pragma unroll
    for (int i = 0; i < 2; i++)
#pragma unroll
        for (int Nt = 0; Nt < 4; Nt++)
#pragma unroll
            for (int j = 0; j < 4; j++) acc[i][Nt][j] = 0.f;

    const uint32_t abase = smem_u32_of(smem)
                         + (uint32_t)((lane & 15) * SLOT + (lane >> 4) * 16)
                         + (uint32_t)(wid * 34 * SLOT);

#pragma unroll
    for (int st = 0; st < 18; st++) {
        const int t  = st >> 1;
        const int s2 = st & 1;
        const int ky = (t >= 6) ? 2 : (t >= 3 ? 1 : 0);
        const int kx = t - ky * 3;

        uint2 b0 = wp[0], b1 = wp[32], b2 = wp[64], b3 = wp[96];
        wp += 128;

        const uint32_t rowaddr = abase + (uint32_t)(s2 * S2OFF + (ky * 34 + kx) * SLOT);
#pragma unroll
        for (int i = 0; i < 2; i++) {
            uint32_t a0, a1, a2, a3;
            LDSM_X4(a0, a1, a2, a3, rowaddr + (uint32_t)(i * 16 * SLOT));
#define MMA_NT(BB, NT)                                                          \
            asm volatile(                                                       \
                "mma.sync.aligned.m16n8k16.row.col.f32.f16.f16.f32 "            \
                "{%0,%1,%2,%3}, {%4,%5,%6,%7}, {%8,%9}, {%0,%1,%2,%3};"         \
                : "+f"(acc[i][NT][0]), "+f"(acc[i][NT][1]),                     \
                  "+f"(acc[i][NT][2]), "+f"(acc[i][NT][3])                      \
                : "r"(a0), "r"(a1), "r"(a2), "r"(a3),                           \
                  "r"(BB.x), "r"(BB.y))
            MMA_NT(b0, 0); MMA_NT(b1, 1); MMA_NT(b2, 2); MMA_NT(b3, 3);
#undef MMA_NT
        }
    }

    // ---- epilogue: bias + clampnorm + one STG.128 per pixel per lane ---------
    // lane tig owns couts 8*tig..8*tig+7: half2 slot Nt = channels (8tig+2Nt,+1)
    const float4* bp = (const float4*)(bias + 8 * tig);
    const float4 bsa = bp[0], bsb = bp[1];
    const float bch[8] = {bsa.x, bsa.y, bsa.z, bsa.w, bsb.x, bsb.y, bsb.z, bsb.w};

    uint4* o4 = (uint4*)(MODE == 0 ? g_bufB : g_bufA) + (size_t)n * PLANE * 4;
    const int pixrow = (gy0 + wid) * WW + gx0;
#pragma unroll
    for (int i = 0; i < 2; i++) {
        float vA[8], vB[8];
        float ssA = 0.f, ssB = 0.f;
#pragma unroll
        for (int Nt = 0; Nt < 4; Nt++) {
            float a0 = acc[i][Nt][0] + bch[2 * Nt];
            float a1 = acc[i][Nt][1] + bch[2 * Nt + 1];
            float b0 = acc[i][Nt][2] + bch[2 * Nt];
            float b1 = acc[i][Nt][3] + bch[2 * Nt + 1];
            vA[2 * Nt] = a0; vA[2 * Nt + 1] = a1;
            vB[2 * Nt] = b0; vB[2 * Nt + 1] = b1;
            ssA += a0 * a0 + a1 * a1;
            ssB += b0 * b0 + b1 * b1;
        }
        ssA += __shfl_xor_sync(0xffffffffu, ssA, 1);
        ssA += __shfl_xor_sync(0xffffffffu, ssA, 2);
        ssB += __shfl_xor_sync(0xffffffffu, ssB, 1);
        ssB += __shfl_xor_sync(0xffffffffu, ssB, 2);
        float nA = sqrtf(ssA), nB = sqrtf(ssB);
        float fA = (nA > R_CLAMP) ? (R_CLAMP / nA) : 1.0f;
        float fB = (nB > R_CLAMP) ? (R_CLAMP / nB) : 1.0f;
        int pixA = pixrow + i * 16 + gid;
        int pixB = pixA + 8;
        uint32_t hA[4], hB[4];
#pragma unroll
        for (int Nt = 0; Nt < 4; Nt++) {
            __half2 a = __floats2half2_rn(vA[2 * Nt] * fA, vA[2 * Nt + 1] * fA);
            __half2 b = __floats2half2_rn(vB[2 * Nt] * fB, vB[2 * Nt + 1] * fB);
            hA[Nt] = *(const uint32_t*)&a;
            hB[Nt] = *(const uint32_t*)&b;
        }
        o4[pixA * 4 + tig] = make_uint4(hA[0], hA[1], hA[2], hA[3]);
        o4[pixB * 4 + tig] = make_uint4(hB[0], hB[1], hB[2], hB[3]);
    }
}

// ---- per-channel sum/sumsq over channel-last fp16 buffer (uint4 loads) -------
__global__ void __launch_bounds__(256) stats_kernel(int statOff, int which) {
    const uint4* b4 = (const uint4*)(which ? g_bufA : g_bufB);
    const int q  = threadIdx.x & 3;      // channel group 8q..8q+7
    const int pr = threadIdx.x >> 2;     // 0..63
    const size_t base = (size_t)blockIdx.x * 1024;
    float s[8], sq[8];
#pragma unroll
    for (int j = 0; j < 8; j++) { s[j] = 0.f; sq[j] = 0.f; }
    for (int pp = pr; pp < 1024; pp += 64) {
        uint4 v = b4[(base + pp) * 4 + q];
        const uint32_t w_[4] = {v.x, v.y, v.z, v.w};
#pragma unroll
        for (int j2 = 0; j2 < 4; j2++) {
            float2 f = __half22float2(*(const __half2*)&w_[j2]);
            s[2*j2]   += f.x;  sq[2*j2]   += f.x * f.x;
            s[2*j2+1] += f.y;  sq[2*j2+1] += f.y * f.y;
        }
    }
#pragma unroll
    for (int j = 0; j < 8; j++) {
#pragma unroll
        for (int o = 4; o <= 16; o <<= 1) {
            s[j]  += __shfl_xor_sync(0xffffffffu, s[j],  o);
            sq[j] += __shfl_xor_sync(0xffffffffu, sq[j], o);
        }
    }
    __shared__ float ssum[64];
    if (threadIdx.x < 64) ssum[threadIdx.x] = 0.f;
    __syncthreads();
    if ((threadIdx.x & 31) < 4) {
#pragma unroll
        for (int j = 0; j < 8; j++) {
            atomicAdd(&ssum[q * 8 + j],      s[j]);
            atomicAdd(&ssum[32 + q * 8 + j], sq[j]);
        }
    }
    __syncthreads();
    if (threadIdx.x < 64) atomicAdd(&g_stats[statOff + threadIdx.x], ssum[threadIdx.x]);
}

// ---- bn2 + clamp + relu + expmap0 + project : bufA (ch-last) -> out (NCHW) ---
__global__ void __launch_bounds__(256) final_kernel(const float* __restrict__ gamma,
                                                    const float* __restrict__ beta,
                                                    float* __restrict__ out) {
    __shared__ float s_aff[64];
    if (threadIdx.x < 32) {
        int c = threadIdx.x;
        const float inv = 1.0f / (float)NPIX;
        float m   = g_stats[64 + c] * inv;
        float var = fmaxf(g_stats[96 + c] * inv - m * m, 0.f);
        float is  = rsqrtf(var + 1e-5f);
        float sc  = gamma[c] * is;
        s_aff[c]      = sc;
        s_aff[32 + c] = beta[c] - m * sc;
    }
    __syncthreads();

    int q  = blockIdx.x * 64 + (threadIdx.x >> 2);
    int lq = threadIdx.x & 3;
    int c0 = lq * 8;
    int n  = q >> 16, hw = q & 65535;

    uint4 hv = ((const uint4*)g_bufA)[(size_t)q * 4 + lq];
    const uint32_t hw_[4] = {hv.x, hv.y, hv.z, hv.w};
    float u[8]; float ss = 0.f;
#pragma unroll
    for (int j2 = 0; j2 < 4; j2++) {
        float2 f = __half22float2(*(const __half2*)&hw_[j2]);
        float u0 = f.x * s_aff[c0 + 2*j2]     + s_aff[32 + c0 + 2*j2];
        float u1 = f.y * s_aff[c0 + 2*j2 + 1] + s_aff[32 + c0 + 2*j2 + 1];
        u[2*j2] = u0; u[2*j2+1] = u1;
        ss += u0 * u0 + u1 * u1;
    }
    ss += __shfl_xor_sync(0xffffffffu, ss, 1);
    ss += __shfl_xor_sync(0xffffffffu, ss, 2);
    float nrm = sqrtf(ss);
    float f1 = (nrm > R_CLAMP) ? (R_CLAMP / nrm) : 1.0f;
    float ss2 = 0.f;
#pragma unroll
    for (int j = 0; j < 8; j++) { u[j] = fmaxf(u[j] * f1, 0.f); ss2 += u[j] * u[j]; }
    ss2 += __shfl_xor_sync(0xffffffffu, ss2, 1);
    ss2 += __shfl_xor_sync(0xffffffffu, ss2, 2);
    float nrm2 = sqrtf(ss2);
    float nn  = fmaxf(nrm2, 1e-5f);
    float fac = tanhf(nn) / nn;
    float yn  = fac * nrm2;
    float pm  = fmaxf(yn, 1e-5f);
    float g2  = (pm > MAXN) ? (MAXN / pm) : 1.0f;
    float wsc = fac * g2;
    float* op = out + (size_t)n * IMG + hw;
#pragma unroll
    for (int j = 0; j < 8; j++) op[(c0 + j) << 16] = u[j] * wsc;
}

// ---------------------------------------------------------------------------
extern "C" void kernel_launch(void* const* d_in, const int* in_sizes, int n_in,
                              void* d_out, int out_size) {
    const float* x   = (const float*)d_in[0];
    const float* w1  = (const float*)d_in[1];
    const float* b1  = (const float*)d_in[2];
    const float* g1  = (const float*)d_in[3];
    const float* be1 = (const float*)d_in[4];
    const float* w2  = (const float*)d_in[5];
    const float* b2  = (const float*)d_in[6];
    const float* g2  = (const float*)d_in[7];
    const float* be2 = (const float*)d_in[8];
    float* out = (float*)d_out;

    cudaFuncSetAttribute(conv_fused_kernel<0>,
                         cudaFuncAttributeMaxDynamicSharedMemorySize, SMEM_BYTES);
    cudaFuncSetAttribute(conv_fused_kernel<1>,
                         cudaFuncAttributeMaxDynamicSharedMemorySize, SMEM_BYTES);

    dim3 cgrid(WW / 32, HH / 8, NB);   // 8 x 32 x 8 = 2048 CTAs

    zero_stats_kernel<<<1, 128>>>();                               // 1
    noop_kernel<<<1, 32>>>();                                      // 2 (ncu align)
    pack_w_kernel<<<18, 256>>>(w1, w2);                            // 3

    conv_fused_kernel<0><<<cgrid, 256, SMEM_BYTES>>>(x, b1, nullptr, nullptr); // 4
    stats_kernel<<<512, 256>>>(0, 0);                              // 5

    conv_fused_kernel<1><<<cgrid, 256, SMEM_BYTES>>>(nullptr, b2, g1, be1);    // 6
    stats_kernel<<<512, 256>>>(64, 1);                             // 7

    final_kernel<<<NPIX / 64, 256>>>(g2, be2, out);                // 8
}

// round 15
// speedup vs baseline: 1.1928x; 1.0343x over previous
#include <cuda_runtime.h>
#include <cuda_fp16.h>
#include <cstdint>

// ---------------------------------------------------------------------------
// HVGGBlock in tangent space; convs via mma.sync m16n8k16 fp16 implicit GEMM.
// A tile in smem as [s2-half][pixel][16ch], 48B slots (conflict-free
// ldmatrix.x4). Weight pack permutes couts so each epilogue lane owns a
// contiguous 16B channel chunk -> STG.128 (canonical channel-last preserved).
// CTA = 32x8 outputs, warp = 1 pixel row, __launch_bounds__(256,4) -> 64-reg
// cap, 4 CTAs/SM (46% occ) for latency cover.
//   logmap0(project(expmap0(u))) == clampnorm(u, R), R = artanh(1-1e-4)
// ---------------------------------------------------------------------------

#define NB   8
#define CH   32
#define HH   256
#define WW   256
#define PLANE (HH*WW)
#define IMG   (CH*PLANE)
#define NPIX  (NB*PLANE)

#define R_CLAMP 4.9517188f
#define MAXN    0.9999f

__device__ __align__(16) __half g_bufB[NB*IMG];   // channel-last: [pix][32]
__device__ __align__(16) __half g_bufA[NB*IMG];   // channel-last
__device__ float g_stats[128];   // [0:32) sum1 [32:64) sq1 [64:96) sum2 [96:128) sq2
__device__ __align__(16) uint32_t g_wpack[2*18*4*32*2];  // fp16 B-frags

__global__ void noop_kernel() {}   // profiler launch-alignment

__device__ __forceinline__ uint32_t smem_u32_of(const void* p) {
    uint32_t a;
    asm("{ .reg .u64 t; cvta.to.shared.u64 t, %1; cvt.u32.u64 %0, t; }" : "=r"(a) : "l"(p));
    return a;
}

#define LDSM_X4(r0, r1, r2, r3, addr) \
    asm volatile("ldmatrix.sync.aligned.m8n8.x4.shared.b16 {%0,%1,%2,%3}, [%4];" \
        : "=r"(r0), "=r"(r1), "=r"(r2), "=r"(r3) : "r"(addr))

// ---- weight pack: [layer][step][Nt][lane] -> {b0,b1} fp16x2 ------------------
// cout permutation: column gd of N-tile Nt -> cout = 8*(gd>>1) + 2*Nt + (gd&1)
__global__ void __launch_bounds__(256) pack_w_kernel(const float* __restrict__ w1,
                                                     const float* __restrict__ w2) {
    int id = blockIdx.x * 256 + threadIdx.x;
    if (id >= 4608) return;
    int lay = id / 2304;
    int r   = id - lay * 2304;
    int l   = r & 31;
    int Nt  = (r >> 5) & 3;
    int st  = r >> 7;                 // 0..17
    int t   = st >> 1, s2 = st & 1;
    int tig = l & 3, gd = l >> 2;
    int co  = 8 * (gd >> 1) + 2 * Nt + (gd & 1);   // permuted cout
    int ch0 = s2 * 16 + 2 * tig;
    const float* w = lay ? w2 : w1;
    __half2 h0 = __floats2half2_rn(w[(co * CH + ch0    ) * 9 + t],
                                   w[(co * CH + ch0 + 1) * 9 + t]);
    __half2 h1 = __floats2half2_rn(w[(co * CH + ch0 + 8) * 9 + t],
                                   w[(co * CH + ch0 + 9) * 9 + t]);
    uint2* dst = (uint2*)(g_wpack + lay * 4608);
    dst[(st * 4 + Nt) * 32 + l] = make_uint2(*(const uint32_t*)&h0,
                                             *(const uint32_t*)&h1);
}

__global__ void zero_stats_kernel() {
    int t = threadIdx.x;
    if (t < 128) g_stats[t] = 0.f;
}

// ---- fused conv kernel -------------------------------------------------------
#define SLOT    48
#define S2OFF   (340*SLOT)            // 16320
#define SMEM_BYTES (2*S2OFF)          // 32640 dynamic

// MODE 0: src = x (fp32 NCHW), logmap, dst = g_bufB (fp16 ch-last)
// MODE 1: src = g_bufB, BN(stats[0:64])+clamp+relu, dst = g_bufA
template<int MODE>
__global__ void __launch_bounds__(256, 4)
conv_fused_kernel(const float* __restrict__ ext, const float* __restrict__ bias,
                  const float* __restrict__ gamma, const float* __restrict__ beta) {
    extern __shared__ __align__(16) char smem[];
    __shared__ float s_aff[64];

    const int tid  = threadIdx.x;
    const int wid  = tid >> 5;
    const int lane = tid & 31;
    const int gid  = lane >> 2;
    const int tig  = lane & 3;
    const int n    = blockIdx.z;
    const int gy0  = blockIdx.y * 8;
    const int gx0  = blockIdx.x * 32;

    if (MODE == 1) {
        if (tid < 32) {
            const float inv = 1.0f / (float)NPIX;
            float m   = g_stats[tid] * inv;
            float var = fmaxf(g_stats[32 + tid] * inv - m * m, 0.f);
            float is  = rsqrtf(var + 1e-5f);
            float sc  = gamma[tid] * is;
            s_aff[tid]      = sc;
            s_aff[32 + tid] = beta[tid] - m * sc;
        }
        __syncthreads();
    }

    // ---- build: quad-cooperative; lane's 8 channels are one 16B STS.128 ------
    const int lq = tid & 3;          // channels 8*lq .. 8*lq+7
    const int c0 = lq * 8;
    char* wr = smem + (lq >> 1) * S2OFF + (lq & 1) * 16;
    for (int p0 = tid >> 2; p0 < 384; p0 += 64) {
        bool act = (p0 < 340);
        int r = p0 / 34, c = p0 - r * 34;
        int gy = gy0 + r - 1, gx = gx0 + c - 1;
        bool inb = act && ((unsigned)gy < 256u) && ((unsigned)gx < 256u);
        float v[8]; float ss = 0.f;
        if (inb) {
            if (MODE == 0) {
                const float* sp = ext + n * IMG + c0 * PLANE + gy * WW + gx;
#pragma unroll
                for (int j = 0; j < 8; j++) { v[j] = sp[j * PLANE]; ss += v[j] * v[j]; }
            } else {
                uint4 hv = ((const uint4*)g_bufB)[(n * PLANE + gy * WW + gx) * 4 + lq];
                const uint32_t hw_[4] = {hv.x, hv.y, hv.z, hv.w};
#pragma unroll
                for (int j2 = 0; j2 < 4; j2++) {
                    float2 f = __half22float2(*(const __half2*)&hw_[j2]);
                    float u0 = f.x * s_aff[c0 + 2*j2]     + s_aff[32 + c0 + 2*j2];
                    float u1 = f.y * s_aff[c0 + 2*j2 + 1] + s_aff[32 + c0 + 2*j2 + 1];
                    v[2*j2] = u0; v[2*j2+1] = u1;
                    ss += u0 * u0 + u1 * u1;
                }
            }
        } else {
#pragma unroll
            for (int j = 0; j < 8; j++) v[j] = 0.f;
        }
        ss += __shfl_xor_sync(0xffffffffu, ss, 1);
        ss += __shfl_xor_sync(0xffffffffu, ss, 2);
        float f;
        if (MODE == 0) {
            float nrm = sqrtf(ss);
            float nn  = fmaxf(nrm, 1e-5f);
            float t   = fminf(nn, 1.f - 1e-5f);
            f = 0.5f * (log1pf(t) - log1pf(-t)) / nn;              // logmap0
        } else {
            float nrm = sqrtf(ss);
            f = (nrm > R_CLAMP) ? (R_CLAMP / nrm) : 1.0f;          // clampnorm
        }
        if (act) {
            uint32_t hh[4];
#pragma unroll
            for (int j = 0; j < 4; j++) {
                float u0 = v[2*j] * f, u1 = v[2*j+1] * f;
                if (MODE == 1) { u0 = fmaxf(u0, 0.f); u1 = fmaxf(u1, 0.f); }
                __half2 h = __floats2half2_rn(u0, u1);
                hh[j] = *(const uint32_t*)&h;
            }
            *(uint4*)(wr + p0 * SLOT) = make_uint4(hh[0], hh[1], hh[2], hh[3]);
        }
    }
    __syncthreads();

    // ---- implicit GEMM: warp owns 1 pixel row, 2 M-tiles, N=32, K=288 --------
    const uint2* wp = ((const uint2*)(g_wpack + MODE * 4608)) + lane;
    float acc[2][4][4];
#pragma unroll
    for (int i = 0; i < 2; i++)
#pragma unroll
        for (int Nt = 0; Nt < 4; Nt++)
#pragma unroll
            for (int j = 0; j < 4; j++) acc[i][Nt][j] = 0.f;

    const uint32_t abase = smem_u32_of(smem)
                         + (uint32_t)((lane & 15) * SLOT + (lane >> 4) * 16)
                         + (uint32_t)(wid * 34 * SLOT);

#pragma unroll
    for (int st = 0; st < 18; st++) {
        const int t  = st >> 1;
        const int s2 = st & 1;
        const int ky = (t >= 6) ? 2 : (t >= 3 ? 1 : 0);
        const int kx = t - ky * 3;

        uint2 b0 = wp[0], b1 = wp[32], b2 = wp[64], b3 = wp[96];
        wp += 128;

        const uint32_t rowaddr = abase + (uint32_t)(s2 * S2OFF + (ky * 34 + kx) * SLOT);
#pragma unroll
        for (int i = 0; i < 2; i++) {
            uint32_t a0, a1, a2, a3;
            LDSM_X4(a0, a1, a2, a3, rowaddr + (uint32_t)(i * 16 * SLOT));
#define MMA_NT(BB, NT)                                                          \
            asm volatile(                                                       \
                "mma.sync.aligned.m16n8k16.row.col.f32.f16.f16.f32 "            \
                "{%0,%1,%2,%3}, {%4,%5,%6,%7}, {%8,%9}, {%0,%1,%2,%3};"         \
                : "+f"(acc[i][NT][0]), "+f"(acc[i][NT][1]),                     \
                  "+f"(acc[i][NT][2]), "+f"(acc[i][NT][3])                      \
                : "r"(a0), "r"(a1), "r"(a2), "r"(a3),                           \
                  "r"(BB.x), "r"(BB.y))
            MMA_NT(b0, 0); MMA_NT(b1, 1); MMA_NT(b2, 2); MMA_NT(b3, 3);
#undef MMA_NT
        }
    }

    // ---- epilogue: bias + clampnorm + one STG.128 per pixel per lane ---------
    const float4* bp = (const float4*)(bias + 8 * tig);
    const float4 bsa = bp[0], bsb = bp[1];
    const float bch[8] = {bsa.x, bsa.y, bsa.z, bsa.w, bsb.x, bsb.y, bsb.z, bsb.w};

    uint4* o4 = (uint4*)(MODE == 0 ? g_bufB : g_bufA) + (size_t)n * PLANE * 4;
    const int pixrow = (gy0 + wid) * WW + gx0;
#pragma unroll
    for (int i = 0; i < 2; i++) {
        float vA[8], vB[8];
        float ssA = 0.f, ssB = 0.f;
#pragma unroll
        for (int Nt = 0; Nt < 4; Nt++) {
            float a0 = acc[i][Nt][0] + bch[2 * Nt];
            float a1 = acc[i][Nt][1] + bch[2 * Nt + 1];
            float b0 = acc[i][Nt][2] + bch[2 * Nt];
            float b1 = acc[i][Nt][3] + bch[2 * Nt + 1];
            vA[2 * Nt] = a0; vA[2 * Nt + 1] = a1;
            vB[2 * Nt] = b0; vB[2 * Nt + 1] = b1;
            ssA += a0 * a0 + a1 * a1;
            ssB += b0 * b0 + b1 * b1;
        }
        ssA += __shfl_xor_sync(0xffffffffu, ssA, 1);
        ssA += __shfl_xor_sync(0xffffffffu, ssA, 2);
        ssB += __shfl_xor_sync(0xffffffffu, ssB, 1);
        ssB += __shfl_xor_sync(0xffffffffu, ssB, 2);
        float nA = sqrtf(ssA), nB = sqrtf(ssB);
        float fA = (nA > R_CLAMP) ? (R_CLAMP / nA) : 1.0f;
        float fB = (nB > R_CLAMP) ? (R_CLAMP / nB) : 1.0f;
        int pixA = pixrow + i * 16 + gid;
        int pixB = pixA + 8;
        uint32_t hA[4], hB[4];
#pragma unroll
        for (int Nt = 0; Nt < 4; Nt++) {
            __half2 a = __floats2half2_rn(vA[2 * Nt] * fA, vA[2 * Nt + 1] * fA);
            __half2 b = __floats2half2_rn(vB[2 * Nt] * fB, vB[2 * Nt + 1] * fB);
            hA[Nt] = *(const uint32_t*)&a;
            hB[Nt] = *(const uint32_t*)&b;
        }
        o4[pixA * 4 + tig] = make_uint4(hA[0], hA[1], hA[2], hA[3]);
        o4[pixB * 4 + tig] = make_uint4(hB[0], hB[1], hB[2], hB[3]);
    }
}

// ---- per-channel sum/sumsq over channel-last fp16 buffer (uint4 loads) -------
__global__ void __launch_bounds__(256) stats_kernel(int statOff, int which) {
    const uint4* b4 = (const uint4*)(which ? g_bufA : g_bufB);
    const int q  = threadIdx.x & 3;      // channel group 8q..8q+7
    const int pr = threadIdx.x >> 2;     // 0..63
    const size_t base = (size_t)blockIdx.x * 1024;
    float s[8], sq[8];
#pragma unroll
    for (int j = 0; j < 8; j++) { s[j] = 0.f; sq[j] = 0.f; }
    for (int pp = pr; pp < 1024; pp += 64) {
        uint4 v = b4[(base + pp) * 4 + q];
        const uint32_t w_[4] = {v.x, v.y, v.z, v.w};
#pragma unroll
        for (int j2 = 0; j2 < 4; j2++) {
            float2 f = __half22float2(*(const __half2*)&w_[j2]);
            s[2*j2]   += f.x;  sq[2*j2]   += f.x * f.x;
            s[2*j2+1] += f.y;  sq[2*j2+1] += f.y * f.y;
        }
    }
#pragma unroll
    for (int j = 0; j < 8; j++) {
#pragma unroll
        for (int o = 4; o <= 16; o <<= 1) {
            s[j]  += __shfl_xor_sync(0xffffffffu, s[j],  o);
            sq[j] += __shfl_xor_sync(0xffffffffu, sq[j], o);
        }
    }
    __shared__ float ssum[64];
    if (threadIdx.x < 64) ssum[threadIdx.x] = 0.f;
    __syncthreads();
    if ((threadIdx.x & 31) < 4) {
#pragma unroll
        for (int j = 0; j < 8; j++) {
            atomicAdd(&ssum[q * 8 + j],      s[j]);
            atomicAdd(&ssum[32 + q * 8 + j], sq[j]);
        }
    }
    __syncthreads();
    if (threadIdx.x < 64) atomicAdd(&g_stats[statOff + threadIdx.x], ssum[threadIdx.x]);
}

// ---- bn2 + clamp + relu + expmap0 + project : bufA (ch-last) -> out (NCHW) ---
__global__ void __launch_bounds__(256) final_kernel(const float* __restrict__ gamma,
                                                    const float* __restrict__ beta,
                                                    float* __restrict__ out) {
    __shared__ float s_aff[64];
    if (threadIdx.x < 32) {
        int c = threadIdx.x;
        const float inv = 1.0f / (float)NPIX;
        float m   = g_stats[64 + c] * inv;
        float var = fmaxf(g_stats[96 + c] * inv - m * m, 0.f);
        float is  = rsqrtf(var + 1e-5f);
        float sc  = gamma[c] * is;
        s_aff[c]      = sc;
        s_aff[32 + c] = beta[c] - m * sc;
    }
    __syncthreads();

    int q  = blockIdx.x * 64 + (threadIdx.x >> 2);
    int lq = threadIdx.x & 3;
    int c0 = lq * 8;
    int n  = q >> 16, hw = q & 65535;

    uint4 hv = ((const uint4*)g_bufA)[(size_t)q * 4 + lq];
    const uint32_t hw_[4] = {hv.x, hv.y, hv.z, hv.w};
    float u[8]; float ss = 0.f;
#pragma unroll
    for (int j2 = 0; j2 < 4; j2++) {
        float2 f = __half22float2(*(const __half2*)&hw_[j2]);
        float u0 = f.x * s_aff[c0 + 2*j2]     + s_aff[32 + c0 + 2*j2];
        float u1 = f.y * s_aff[c0 + 2*j2 + 1] + s_aff[32 + c0 + 2*j2 + 1];
        u[2*j2] = u0; u[2*j2+1] = u1;
        ss += u0 * u0 + u1 * u1;
    }
    ss += __shfl_xor_sync(0xffffffffu, ss, 1);
    ss += __shfl_xor_sync(0xffffffffu, ss, 2);
    float nrm = sqrtf(ss);
    float f1 = (nrm > R_CLAMP) ? (R_CLAMP / nrm) : 1.0f;
    float ss2 = 0.f;
#pragma unroll
    for (int j = 0; j < 8; j++) { u[j] = fmaxf(u[j] * f1, 0.f); ss2 += u[j] * u[j]; }
    ss2 += __shfl_xor_sync(0xffffffffu, ss2, 1);
    ss2 += __shfl_xor_sync(0xffffffffu, ss2, 2);
    float nrm2 = sqrtf(ss2);
    float nn  = fmaxf(nrm2, 1e-5f);
    float fac = tanhf(nn) / nn;
    float yn  = fac * nrm2;
    float pm  = fmaxf(yn, 1e-5f);
    float g2  = (pm > MAXN) ? (MAXN / pm) : 1.0f;
    float wsc = fac * g2;
    float* op = out + (size_t)n * IMG + hw;
#pragma unroll
    for (int j = 0; j < 8; j++) op[(c0 + j) << 16] = u[j] * wsc;
}

// ---------------------------------------------------------------------------
extern "C" void kernel_launch(void* const* d_in, const int* in_sizes, int n_in,
                              void* d_out, int out_size) {
    const float* x   = (const float*)d_in[0];
    const float* w1  = (const float*)d_in[1];
    const float* b1  = (const float*)d_in[2];
    const float* g1  = (const float*)d_in[3];
    const float* be1 = (const float*)d_in[4];
    const float* w2  = (const float*)d_in[5];
    const float* b2  = (const float*)d_in[6];
    const float* g2  = (const float*)d_in[7];
    const float* be2 = (const float*)d_in[8];
    float* out = (float*)d_out;

    cudaFuncSetAttribute(conv_fused_kernel<0>,
                         cudaFuncAttributeMaxDynamicSharedMemorySize, SMEM_BYTES);
    cudaFuncSetAttribute(conv_fused_kernel<1>,
                         cudaFuncAttributeMaxDynamicSharedMemorySize, SMEM_BYTES);

    dim3 cgrid(WW / 32, HH / 8, NB);   // 8 x 32 x 8 = 2048 CTAs

    zero_stats_kernel<<<1, 128>>>();                               // 1
    noop_kernel<<<1, 32>>>();                                      // 2 (ncu align)
    pack_w_kernel<<<18, 256>>>(w1, w2);                            // 3

    conv_fused_kernel<0><<<cgrid, 256, SMEM_BYTES>>>(x, b1, nullptr, nullptr); // 4
    stats_kernel<<<512, 256>>>(0, 0);                              // 5

    conv_fused_kernel<1><<<cgrid, 256, SMEM_BYTES>>>(nullptr, b2, g1, be1);    // 6
    stats_kernel<<<512, 256>>>(64, 1);                             // 7

    final_kernel<<<NPIX / 64, 256>>>(g2, be2, out);                // 8
}